// round 8
// baseline (speedup 1.0000x reference)
#include <cuda_runtime.h>

// Problem constants
#define HID   1024
#define BATCH 4
#define SEQ   2048
#define NHEAD 16
#define DH    64
#define NTOK  (BATCH * SEQ)   // 8192

// ---------------------------------------------------------------------------
// Scratch (static __device__ arrays; no allocation anywhere)
// ---------------------------------------------------------------------------
__device__ float g_xln[(size_t)NTOK * HID];   // layernorm output  [tok][1024]
__device__ float g_q[(size_t)NTOK * HID];     // [b*16+h][s][64]
__device__ float g_k[(size_t)NTOK * HID];     // [b*16+h][s][64]
__device__ float g_v[(size_t)NTOK * HID];     // [b*16+h][s][64]
__device__ float g_attn[(size_t)NTOK * HID];  // attention output  [tok][1024]

// ---------------------------------------------------------------------------
// 1) LayerNorm: one block per token, 256 threads, 1 float4 each
// ---------------------------------------------------------------------------
__global__ __launch_bounds__(256) void ln_kernel(
    const float* __restrict__ x,
    const float* __restrict__ gamma,
    const float* __restrict__ beta)
{
    const int t   = blockIdx.x;
    const int tid = threadIdx.x;

    const float4 f = reinterpret_cast<const float4*>(x + (size_t)t * HID)[tid];
    float s  = f.x + f.y + f.z + f.w;
    float ss = f.x * f.x + f.y * f.y + f.z * f.z + f.w * f.w;

    #pragma unroll
    for (int m = 16; m; m >>= 1) {
        s  += __shfl_xor_sync(0xffffffffu, s,  m);
        ss += __shfl_xor_sync(0xffffffffu, ss, m);
    }
    __shared__ float red0[8], red1[8];
    const int w = tid >> 5, l = tid & 31;
    if (l == 0) { red0[w] = s; red1[w] = ss; }
    __syncthreads();
    s = 0.f; ss = 0.f;
    #pragma unroll
    for (int i = 0; i < 8; i++) { s += red0[i]; ss += red1[i]; }

    const float mean = s * (1.0f / HID);
    const float var  = ss * (1.0f / HID) - mean * mean;
    const float rstd = rsqrtf(var + 1e-12f);

    const float4 g = reinterpret_cast<const float4*>(gamma)[tid];
    const float4 b = reinterpret_cast<const float4*>(beta)[tid];
    float4 o;
    o.x = (f.x - mean) * rstd * g.x + b.x;
    o.y = (f.y - mean) * rstd * g.y + b.y;
    o.z = (f.z - mean) * rstd * g.z + b.z;
    o.w = (f.w - mean) * rstd * g.w + b.w;
    reinterpret_cast<float4*>(g_xln + (size_t)t * HID)[tid] = o;
}

// ---------------------------------------------------------------------------
// 2) QKV GEMM: C[8192,3072] = xln @ W_qkv + b_qkv, scattered into q/k/v
//    128x128 tile, BK=8, 256 threads, 8x8 micro-tile
// ---------------------------------------------------------------------------
__global__ __launch_bounds__(256, 2) void qkv_gemm(
    const float* __restrict__ W,
    const float* __restrict__ bias)
{
    const int Kdim = HID;
    const int Ndim = 3 * HID;

    __shared__ float As[8][128];
    __shared__ float Bs[8][128];

    const int tid  = threadIdx.x;
    const int tx   = tid & 15;
    const int ty   = tid >> 4;
    const int row0 = blockIdx.y * 128;
    const int col0 = blockIdx.x * 128;

    float acc[8][8];
    #pragma unroll
    for (int i = 0; i < 8; i++)
        #pragma unroll
        for (int j = 0; j < 8; j++) acc[i][j] = 0.f;

    const int ar = tid >> 1;
    const int ak = (tid & 1) * 4;
    const int br = tid >> 5;
    const int bc = (tid & 31) * 4;

    const float* Aptr = g_xln + (size_t)(row0 + ar) * Kdim + ak;
    const float* Wptr = W + (size_t)br * Ndim + col0 + bc;

    for (int kt = 0; kt < Kdim; kt += 8) {
        const float4 a4 = *reinterpret_cast<const float4*>(Aptr + kt);
        const float4 b4 = *reinterpret_cast<const float4*>(Wptr + (size_t)kt * Ndim);
        __syncthreads();
        As[ak + 0][ar] = a4.x;
        As[ak + 1][ar] = a4.y;
        As[ak + 2][ar] = a4.z;
        As[ak + 3][ar] = a4.w;
        *reinterpret_cast<float4*>(&Bs[br][bc]) = b4;
        __syncthreads();

        #pragma unroll
        for (int kk = 0; kk < 8; kk++) {
            float a[8], b[8];
            *reinterpret_cast<float4*>(a)     = *reinterpret_cast<const float4*>(&As[kk][ty * 8]);
            *reinterpret_cast<float4*>(a + 4) = *reinterpret_cast<const float4*>(&As[kk][ty * 8 + 4]);
            *reinterpret_cast<float4*>(b)     = *reinterpret_cast<const float4*>(&Bs[kk][tx * 8]);
            *reinterpret_cast<float4*>(b + 4) = *reinterpret_cast<const float4*>(&Bs[kk][tx * 8 + 4]);
            #pragma unroll
            for (int i = 0; i < 8; i++)
                #pragma unroll
                for (int j = 0; j < 8; j++)
                    acc[i][j] += a[i] * b[j];
        }
    }

    // Epilogue: add bias, scatter to q/k/v in [b*16+h][s][d] layout.
    const int part = col0 >> 10;  // whole 128-col block lies in one part
    float* dst = (part == 0) ? g_q : (part == 1) ? g_k : g_v;

    #pragma unroll
    for (int i = 0; i < 8; i++) {
        const int r  = row0 + ty * 8 + i;
        const int b_ = r >> 11;
        const int s_ = r & 2047;
        #pragma unroll
        for (int j = 0; j < 8; j += 4) {
            const int n = col0 + tx * 8 + j;
            float4 c;
            c.x = acc[i][j + 0] + bias[n + 0];
            c.y = acc[i][j + 1] + bias[n + 1];
            c.z = acc[i][j + 2] + bias[n + 2];
            c.w = acc[i][j + 3] + bias[n + 3];
            const int h = (n & 1023) >> 6;
            const int d = n & 63;
            *reinterpret_cast<float4*>(
                &dst[(((size_t)(b_ * NHEAD + h)) * SEQ + s_) * DH + d]) = c;
        }
    }
}

// ---------------------------------------------------------------------------
// 3) Flash attention (fp32, online softmax)
//    grid = (SEQ/64, BATCH*NHEAD), 256 threads (16x16)
//    smem: Qs 64x64 | KV 64x64 (K swizzled / V plain, time-shared) | P 64x64
// ---------------------------------------------------------------------------
__global__ __launch_bounds__(256) void attn_kernel(const float* __restrict__ mask)
{
    __shared__ float Qs[64 * 64];
    __shared__ float KVs[64 * 64];
    __shared__ float Psm[64 * 64];

    const int tid = threadIdx.x;
    const int tx  = tid & 15;
    const int ty  = tid >> 4;
    const int bh  = blockIdx.y;             // 0..63
    const int b   = bh >> 4;
    const int h   = bh & 15;
    const int qt  = blockIdx.x;             // 0..31

    const float* Qg = g_q + ((size_t)bh * SEQ + (size_t)qt * 64) * DH;
    const float* Kg = g_k + (size_t)bh * SEQ * DH;
    const float* Vg = g_v + (size_t)bh * SEQ * DH;
    const float* mk = mask + (size_t)b * SEQ;

    // Load Q tile (64x64): 4 float4 rows-of-16 per pass
    #pragma unroll
    for (int it = 0; it < 4; it++) {
        const int r  = it * 16 + (tid >> 4);
        const int c4 = (tid & 15) * 4;
        *reinterpret_cast<float4*>(&Qs[r * 64 + c4]) =
            *reinterpret_cast<const float4*>(&Qg[(size_t)r * DH + c4]);
    }

    float O[4][4] = {};
    float m_run[4], l_run[4];
    #pragma unroll
    for (int i = 0; i < 4; i++) { m_run[i] = -1e30f; l_run[i] = 0.f; }

    const int qr0 = ty * 4;
    const int dc0 = tx * 4;

    for (int kt = 0; kt < SEQ / 64; kt++) {
        // --- load K tile with float4-granularity XOR swizzle (kc>>2) ---
        #pragma unroll
        for (int it = 0; it < 4; it++) {
            const int r  = it * 16 + (tid >> 4);
            const int d4 = tid & 15;
            const float4 kv4 = *reinterpret_cast<const float4*>(
                &Kg[((size_t)kt * 64 + r) * DH + d4 * 4]);
            *reinterpret_cast<float4*>(
                &KVs[r * 64 + (((d4 ^ (r >> 2)) & 15) << 2)]) = kv4;
        }
        __syncthreads();

        // --- S = Q @ K^T (float4 over d) ---
        float sacc[4][4] = {};
        #pragma unroll
        for (int d4 = 0; d4 < 16; d4++) {
            float4 qv[4], kr[4];
            #pragma unroll
            for (int i = 0; i < 4; i++)
                qv[i] = *reinterpret_cast<const float4*>(&Qs[(qr0 + i) * 64 + d4 * 4]);
            #pragma unroll
            for (int j = 0; j < 4; j++)
                kr[j] = *reinterpret_cast<const float4*>(
                    &KVs[(tx * 4 + j) * 64 + (((d4 ^ tx) & 15) << 2)]);
            #pragma unroll
            for (int i = 0; i < 4; i++)
                #pragma unroll
                for (int j = 0; j < 4; j++)
                    sacc[i][j] += qv[i].x * kr[j].x + qv[i].y * kr[j].y +
                                  qv[i].z * kr[j].z + qv[i].w * kr[j].w;
        }

        // --- online softmax (16-lane shuffle groups per q row) ---
        float mkv[4];
        #pragma unroll
        for (int j = 0; j < 4; j++)
            mkv[j] = __ldg(&mk[kt * 64 + tx * 4 + j]);

        #pragma unroll
        for (int i = 0; i < 4; i++) {
            float sv0 = sacc[i][0] * 0.125f + mkv[0];
            float sv1 = sacc[i][1] * 0.125f + mkv[1];
            float sv2 = sacc[i][2] * 0.125f + mkv[2];
            float sv3 = sacc[i][3] * 0.125f + mkv[3];
            float rm = fmaxf(fmaxf(sv0, sv1), fmaxf(sv2, sv3));
            #pragma unroll
            for (int m = 1; m < 16; m <<= 1)
                rm = fmaxf(rm, __shfl_xor_sync(0xffffffffu, rm, m));
            const float mnew = fmaxf(m_run[i], rm);
            const float corr = __expf(m_run[i] - mnew);
            const float p0 = __expf(sv0 - mnew);
            const float p1 = __expf(sv1 - mnew);
            const float p2 = __expf(sv2 - mnew);
            const float p3 = __expf(sv3 - mnew);
            float rs = p0 + p1 + p2 + p3;
            #pragma unroll
            for (int m = 1; m < 16; m <<= 1)
                rs += __shfl_xor_sync(0xffffffffu, rs, m);
            l_run[i] = l_run[i] * corr + rs;
            m_run[i] = mnew;
            #pragma unroll
            for (int j = 0; j < 4; j++) O[i][j] *= corr;
            *reinterpret_cast<float4*>(&Psm[(qr0 + i) * 64 + (tx << 2)]) =
                make_float4(p0, p1, p2, p3);
        }
        __syncthreads();   // K reads + P writes complete

        // --- load V tile (plain layout, overwrites K buffer) ---
        #pragma unroll
        for (int it = 0; it < 4; it++) {
            const int r  = it * 16 + (tid >> 4);
            const int d4 = tid & 15;
            *reinterpret_cast<float4*>(&KVs[r * 64 + d4 * 4]) =
                *reinterpret_cast<const float4*>(&Vg[((size_t)kt * 64 + r) * DH + d4 * 4]);
        }
        __syncthreads();

        // --- O += P @ V (float4 over kv) ---
        #pragma unroll
        for (int k4 = 0; k4 < 16; k4++) {
            float4 pv[4];
            #pragma unroll
            for (int i = 0; i < 4; i++)
                pv[i] = *reinterpret_cast<const float4*>(&Psm[(qr0 + i) * 64 + k4 * 4]);
            const float4 vv0 = *reinterpret_cast<const float4*>(&KVs[(k4 * 4 + 0) * 64 + dc0]);
            const float4 vv1 = *reinterpret_cast<const float4*>(&KVs[(k4 * 4 + 1) * 64 + dc0]);
            const float4 vv2 = *reinterpret_cast<const float4*>(&KVs[(k4 * 4 + 2) * 64 + dc0]);
            const float4 vv3 = *reinterpret_cast<const float4*>(&KVs[(k4 * 4 + 3) * 64 + dc0]);
            #pragma unroll
            for (int i = 0; i < 4; i++) {
                O[i][0] += pv[i].x * vv0.x + pv[i].y * vv1.x + pv[i].z * vv2.x + pv[i].w * vv3.x;
                O[i][1] += pv[i].x * vv0.y + pv[i].y * vv1.y + pv[i].z * vv2.y + pv[i].w * vv3.y;
                O[i][2] += pv[i].x * vv0.z + pv[i].y * vv1.z + pv[i].z * vv2.z + pv[i].w * vv3.z;
                O[i][3] += pv[i].x * vv0.w + pv[i].y * vv1.w + pv[i].z * vv2.w + pv[i].w * vv3.w;
            }
        }
        __syncthreads();   // PV done before next K overwrite
    }

    // --- normalize and write to g_attn [b][s][h*64+d] ---
    #pragma unroll
    for (int i = 0; i < 4; i++) {
        const float inv = 1.0f / l_run[i];
        const int srow = qt * 64 + qr0 + i;
        const float4 o4 = make_float4(O[i][0] * inv, O[i][1] * inv,
                                      O[i][2] * inv, O[i][3] * inv);
        *reinterpret_cast<float4*>(
            &g_attn[((size_t)b * SEQ + srow) * HID + h * DH + dc0]) = o4;
    }
}

// ---------------------------------------------------------------------------
// 4) Out GEMM: out = attn @ W_out + b_out + hidden  (128x128x8 tile)
// ---------------------------------------------------------------------------
__global__ __launch_bounds__(256, 2) void out_gemm(
    const float* __restrict__ W,
    const float* __restrict__ bias,
    const float* __restrict__ resid,
    float* __restrict__ out)
{
    const int Kdim = HID;
    const int Ndim = HID;

    __shared__ float As[8][128];
    __shared__ float Bs[8][128];

    const int tid  = threadIdx.x;
    const int tx   = tid & 15;
    const int ty   = tid >> 4;
    const int row0 = blockIdx.y * 128;
    const int col0 = blockIdx.x * 128;

    float acc[8][8];
    #pragma unroll
    for (int i = 0; i < 8; i++)
        #pragma unroll
        for (int j = 0; j < 8; j++) acc[i][j] = 0.f;

    const int ar = tid >> 1;
    const int ak = (tid & 1) * 4;
    const int br = tid >> 5;
    const int bc = (tid & 31) * 4;

    const float* Aptr = g_attn + (size_t)(row0 + ar) * Kdim + ak;
    const float* Wptr = W + (size_t)br * Ndim + col0 + bc;

    for (int kt = 0; kt < Kdim; kt += 8) {
        const float4 a4 = *reinterpret_cast<const float4*>(Aptr + kt);
        const float4 b4 = *reinterpret_cast<const float4*>(Wptr + (size_t)kt * Ndim);
        __syncthreads();
        As[ak + 0][ar] = a4.x;
        As[ak + 1][ar] = a4.y;
        As[ak + 2][ar] = a4.z;
        As[ak + 3][ar] = a4.w;
        *reinterpret_cast<float4*>(&Bs[br][bc]) = b4;
        __syncthreads();

        #pragma unroll
        for (int kk = 0; kk < 8; kk++) {
            float a[8], b[8];
            *reinterpret_cast<float4*>(a)     = *reinterpret_cast<const float4*>(&As[kk][ty * 8]);
            *reinterpret_cast<float4*>(a + 4) = *reinterpret_cast<const float4*>(&As[kk][ty * 8 + 4]);
            *reinterpret_cast<float4*>(b)     = *reinterpret_cast<const float4*>(&Bs[kk][tx * 8]);
            *reinterpret_cast<float4*>(b + 4) = *reinterpret_cast<const float4*>(&Bs[kk][tx * 8 + 4]);
            #pragma unroll
            for (int i = 0; i < 8; i++)
                #pragma unroll
                for (int j = 0; j < 8; j++)
                    acc[i][j] += a[i] * b[j];
        }
    }

    #pragma unroll
    for (int i = 0; i < 8; i++) {
        const int r = row0 + ty * 8 + i;
        #pragma unroll
        for (int j = 0; j < 8; j += 4) {
            const int n = col0 + tx * 8 + j;
            const size_t off = (size_t)r * HID + n;
            const float4 rz = *reinterpret_cast<const float4*>(&resid[off]);
            float4 c;
            c.x = acc[i][j + 0] + bias[n + 0] + rz.x;
            c.y = acc[i][j + 1] + bias[n + 1] + rz.y;
            c.z = acc[i][j + 2] + bias[n + 2] + rz.z;
            c.w = acc[i][j + 3] + bias[n + 3] + rz.w;
            *reinterpret_cast<float4*>(&out[off]) = c;
        }
    }
}

// ---------------------------------------------------------------------------
// kernel_launch: 4 graph-capturable kernel launches, no allocations/syncs
// ---------------------------------------------------------------------------
extern "C" void kernel_launch(void* const* d_in, const int* in_sizes, int n_in,
                              void* d_out, int out_size)
{
    (void)in_sizes; (void)n_in; (void)out_size;
    const float* hidden = (const float*)d_in[0];
    const float* mask   = (const float*)d_in[1];
    const float* gamma  = (const float*)d_in[2];
    const float* beta   = (const float*)d_in[3];
    const float* Wqkv   = (const float*)d_in[4];
    const float* bqkv   = (const float*)d_in[5];
    const float* Wout   = (const float*)d_in[6];
    const float* bout   = (const float*)d_in[7];
    float* out = (float*)d_out;

    ln_kernel<<<NTOK, 256>>>(hidden, gamma, beta);
    qkv_gemm<<<dim3(3 * HID / 128, NTOK / 128), 256>>>(Wqkv, bqkv);
    attn_kernel<<<dim3(SEQ / 64, BATCH * NHEAD), 256>>>(mask);
    out_gemm<<<dim3(HID / 128, NTOK / 128), 256>>>(Wout, bout, hidden, out);
}

// round 10
// speedup vs baseline: 1.4689x; 1.4689x over previous
#include <cuda_runtime.h>
#include <cuda_bf16.h>
#include <cstdint>

// Problem constants
#define HID   1024
#define BATCH 4
#define SEQ   2048
#define NHEAD 16
#define DH    64
#define NTOK  (BATCH * SEQ)   // 8192

// ---------------------------------------------------------------------------
// Scratch (static __device__ arrays; no allocation anywhere)
// ---------------------------------------------------------------------------
__device__ float g_q[(size_t)NTOK * HID];     // [b*16+h][s][64]
__device__ float g_k[(size_t)NTOK * HID];
__device__ float g_v[(size_t)NTOK * HID];

// bf16-split activations (LN output, later attention output)
__device__ __nv_bfloat16 g_ah[(size_t)NTOK * HID];
__device__ __nv_bfloat16 g_al[(size_t)NTOK * HID];
// bf16-split transposed weights [N][K]
__device__ __nv_bfloat16 g_wqh[(size_t)3 * HID * HID];
__device__ __nv_bfloat16 g_wql[(size_t)3 * HID * HID];
__device__ __nv_bfloat16 g_woh[(size_t)HID * HID];
__device__ __nv_bfloat16 g_wol[(size_t)HID * HID];

// ---------------------------------------------------------------------------
// Warp-MMA helpers (family-compatible: ldmatrix + mma.sync + cp.async)
// ---------------------------------------------------------------------------
__device__ __forceinline__ uint32_t smem_u32(const void* p) {
    return (uint32_t)__cvta_generic_to_shared(p);
}

__device__ __forceinline__ void cp16(uint32_t dst, const void* src) {
    asm volatile("cp.async.cg.shared.global [%0], [%1], 16;" :: "r"(dst), "l"(src));
}
#define CP_COMMIT() asm volatile("cp.async.commit_group;" ::: "memory")
#define CP_WAIT0()  asm volatile("cp.async.wait_group 0;" ::: "memory")
#define CP_WAIT1()  asm volatile("cp.async.wait_group 1;" ::: "memory")

__device__ __forceinline__ void ldsm_x4(uint32_t* r, uint32_t addr) {
    asm volatile("ldmatrix.sync.aligned.m8n8.x4.shared.b16 {%0,%1,%2,%3}, [%4];"
        : "=r"(r[0]), "=r"(r[1]), "=r"(r[2]), "=r"(r[3]) : "r"(addr));
}

__device__ __forceinline__ void mma_bf16(float* c, const uint32_t* a, const uint32_t* b) {
    asm volatile(
        "mma.sync.aligned.m16n8k16.row.col.f32.bf16.bf16.f32 "
        "{%0,%1,%2,%3}, {%4,%5,%6,%7}, {%8,%9}, {%0,%1,%2,%3};"
        : "+f"(c[0]), "+f"(c[1]), "+f"(c[2]), "+f"(c[3])
        : "r"(a[0]), "r"(a[1]), "r"(a[2]), "r"(a[3]), "r"(b[0]), "r"(b[1]));
}

// ---------------------------------------------------------------------------
// 1) LayerNorm fused with bf16 hi/lo split -> g_ah / g_al
// ---------------------------------------------------------------------------
__global__ __launch_bounds__(256) void ln_kernel(
    const float* __restrict__ x,
    const float* __restrict__ gamma,
    const float* __restrict__ beta)
{
    const int t   = blockIdx.x;
    const int tid = threadIdx.x;

    const float4 f = reinterpret_cast<const float4*>(x + (size_t)t * HID)[tid];
    float s  = f.x + f.y + f.z + f.w;
    float ss = f.x * f.x + f.y * f.y + f.z * f.z + f.w * f.w;

    #pragma unroll
    for (int m = 16; m; m >>= 1) {
        s  += __shfl_xor_sync(0xffffffffu, s,  m);
        ss += __shfl_xor_sync(0xffffffffu, ss, m);
    }
    __shared__ float red0[8], red1[8];
    const int w = tid >> 5, l = tid & 31;
    if (l == 0) { red0[w] = s; red1[w] = ss; }
    __syncthreads();
    s = 0.f; ss = 0.f;
    #pragma unroll
    for (int i = 0; i < 8; i++) { s += red0[i]; ss += red1[i]; }

    const float mean = s * (1.0f / HID);
    const float var  = ss * (1.0f / HID) - mean * mean;
    const float rstd = rsqrtf(var + 1e-12f);

    const float4 g = reinterpret_cast<const float4*>(gamma)[tid];
    const float4 b = reinterpret_cast<const float4*>(beta)[tid];
    float o[4];
    o[0] = (f.x - mean) * rstd * g.x + b.x;
    o[1] = (f.y - mean) * rstd * g.y + b.y;
    o[2] = (f.z - mean) * rstd * g.z + b.z;
    o[3] = (f.w - mean) * rstd * g.w + b.w;

    const size_t off = (size_t)t * HID + tid * 4;
    __nv_bfloat16 h[4], lo[4];
    #pragma unroll
    for (int i = 0; i < 4; i++) {
        h[i]  = __float2bfloat16(o[i]);
        lo[i] = __float2bfloat16(o[i] - __bfloat162float(h[i]));
    }
    *reinterpret_cast<__nv_bfloat162*>(g_ah + off)     = __halves2bfloat162(h[0], h[1]);
    *reinterpret_cast<__nv_bfloat162*>(g_ah + off + 2) = __halves2bfloat162(h[2], h[3]);
    *reinterpret_cast<__nv_bfloat162*>(g_al + off)     = __halves2bfloat162(lo[0], lo[1]);
    *reinterpret_cast<__nv_bfloat162*>(g_al + off + 2) = __halves2bfloat162(lo[2], lo[3]);
}

// ---------------------------------------------------------------------------
// 2) Transpose + split weights: W [K=1024][Ndim] -> T{h,l} [Ndim][1024]
// ---------------------------------------------------------------------------
__global__ __launch_bounds__(256) void conv_w(const float* __restrict__ W,
                                              int which, int Ndim)
{
    __nv_bfloat16* Th = which ? g_woh : g_wqh;
    __nv_bfloat16* Tl = which ? g_wol : g_wql;

    __shared__ float t[32][33];
    const int n0 = blockIdx.x * 32, k0 = blockIdx.y * 32;
    const int x = threadIdx.x, y = threadIdx.y;

    #pragma unroll
    for (int i = 0; i < 4; i++)
        t[y + i * 8][x] = W[(size_t)(k0 + y + i * 8) * Ndim + n0 + x];
    __syncthreads();

    #pragma unroll
    for (int i = 0; i < 4; i++) {
        const int n = n0 + y + i * 8;
        const int k = k0 + x;
        const float v = t[x][y + i * 8];
        const __nv_bfloat16 h = __float2bfloat16(v);
        Th[(size_t)n * HID + k] = h;
        Tl[(size_t)n * HID + k] = __float2bfloat16(v - __bfloat162float(h));
    }
}

// ---------------------------------------------------------------------------
// 3) Tensor-core GEMM (mma.sync bf16, 3-term split):
//    D[M=8192, N] = A @ W^T (+bias [, +resid])
//    CTA tile 128x128, BK=32, 8 warps (2x4), warp tile 64x32.
//    which: 0 = QKV (scatter q/k/v), 1 = OUT (bias+resid -> outp)
//    Smem buffer: AH|AL|BH|BL each 128x32 bf16 = 8KB, XOR-swizzled; x2 buffers.
// ---------------------------------------------------------------------------
#define MM_SMEM 65536

__global__ __launch_bounds__(256) void mm_kernel(
    int which, const float* __restrict__ bias,
    const float* __restrict__ resid, float* __restrict__ outp)
{
    extern __shared__ char smem[];
    const uint32_t sb = smem_u32(smem);
    const int tid  = threadIdx.x;
    const int lane = tid & 31;
    const int wid  = tid >> 5;
    const int wm   = wid >> 2;        // 0..1
    const int wn   = wid & 3;         // 0..3
    const int row0 = blockIdx.y * 128;
    const int col0 = blockIdx.x * 128;

    const __nv_bfloat16* Ah = g_ah + (size_t)row0 * HID;
    const __nv_bfloat16* Al = g_al + (size_t)row0 * HID;
    const __nv_bfloat16* Bh = (which ? g_woh : g_wqh) + (size_t)col0 * HID;
    const __nv_bfloat16* Bl = (which ? g_wol : g_wql) + (size_t)col0 * HID;

    float C[4][4][4];
    #pragma unroll
    for (int i = 0; i < 4; i++)
        #pragma unroll
        for (int j = 0; j < 4; j++)
            #pragma unroll
            for (int k = 0; k < 4; k++) C[i][j][k] = 0.f;

    // ---- async slab loader: 2048 16B chunks, 8 per thread ----
    auto load_slab = [&](int kt, int buf) {
        const uint32_t base = sb + (uint32_t)buf * 32768u;
        #pragma unroll
        for (int it = 0; it < 8; it++) {
            const int c   = it * 256 + tid;
            const int arr = c >> 9;          // 0:AH 1:AL 2:BH 3:BL
            const int cc  = c & 511;
            const int r   = cc >> 2;         // row 0..127
            const int j   = cc & 3;          // 16B chunk in 64B row
            const uint32_t soff = (uint32_t)(arr * 8192 + r * 64 +
                                             ((j ^ ((r >> 1) & 3)) << 4));
            const __nv_bfloat16* src =
                (arr == 0 ? Ah : arr == 1 ? Al : arr == 2 ? Bh : Bl)
                + (size_t)r * HID + kt * 32 + j * 8;
            cp16(base + soff, src);
        }
    };

    // ---- compute one 32-wide K slab from buffer buf ----
    auto compute = [&](int buf) {
        const uint32_t base = sb + (uint32_t)buf * 32768u;
        #pragma unroll
        for (int ks = 0; ks < 2; ks++) {
            uint32_t ah[4][4], al[4][4], bh[4][2], bl[4][2];
            #pragma unroll
            for (int mt = 0; mt < 4; mt++) {
                const int r  = wm * 64 + mt * 16 + (lane & 15);
                const int jc = ks * 2 + (lane >> 4);
                const uint32_t addr = base + (uint32_t)(r * 64 +
                                        ((jc ^ ((r >> 1) & 3)) << 4));
                ldsm_x4(ah[mt], addr);
                ldsm_x4(al[mt], addr + 8192);
            }
            #pragma unroll
            for (int p = 0; p < 2; p++) {
                const int r  = wn * 32 + p * 16 + (lane & 7) + ((lane >> 4) << 3);
                const int jc = ks * 2 + ((lane >> 3) & 1);
                const uint32_t addr = base + 16384u + (uint32_t)(r * 64 +
                                        ((jc ^ ((r >> 1) & 3)) << 4));
                uint32_t t4[4];
                ldsm_x4(t4, addr);
                bh[2 * p][0] = t4[0]; bh[2 * p][1] = t4[1];
                bh[2 * p + 1][0] = t4[2]; bh[2 * p + 1][1] = t4[3];
                ldsm_x4(t4, addr + 8192);
                bl[2 * p][0] = t4[0]; bl[2 * p][1] = t4[1];
                bl[2 * p + 1][0] = t4[2]; bl[2 * p + 1][1] = t4[3];
            }
            #pragma unroll
            for (int mt = 0; mt < 4; mt++)
                #pragma unroll
                for (int nt = 0; nt < 4; nt++) {
                    mma_bf16(C[mt][nt], ah[mt], bh[nt]);
                    mma_bf16(C[mt][nt], ah[mt], bl[nt]);
                    mma_bf16(C[mt][nt], al[mt], bh[nt]);
                }
        }
    };

    // ---- pipelined K loop (32 slabs) ----
    load_slab(0, 0);
    CP_COMMIT();
    for (int kt = 0; kt < 32; kt++) {
        const int cur = kt & 1;
        if (kt + 1 < 32) {
            load_slab(kt + 1, cur ^ 1);
            CP_COMMIT();
            CP_WAIT1();
        } else {
            CP_WAIT0();
        }
        __syncthreads();
        compute(cur);
        __syncthreads();
    }

    // ---- epilogue ----
    const int r_lane = lane >> 2;
    const int c_lane = (lane & 3) * 2;

    #pragma unroll
    for (int mt = 0; mt < 4; mt++) {
        #pragma unroll
        for (int half = 0; half < 2; half++) {
            const int m  = row0 + wm * 64 + mt * 16 + r_lane + half * 8;
            const int b_ = m >> 11;
            const int s_ = m & 2047;
            #pragma unroll
            for (int nt = 0; nt < 4; nt++) {
                const int n = col0 + wn * 32 + nt * 8 + c_lane;
                float v0 = C[mt][nt][half * 2 + 0] + bias[n];
                float v1 = C[mt][nt][half * 2 + 1] + bias[n + 1];
                if (which) {
                    const size_t off = (size_t)m * HID + n;
                    const float2 rr = *reinterpret_cast<const float2*>(resid + off);
                    float2 c2 = make_float2(v0 + rr.x, v1 + rr.y);
                    *reinterpret_cast<float2*>(outp + off) = c2;
                } else {
                    const int part = n >> 10;
                    float* dst = (part == 0) ? g_q : (part == 1) ? g_k : g_v;
                    const int h = (n & 1023) >> 6;
                    const int d = n & 63;
                    *reinterpret_cast<float2*>(
                        &dst[(((size_t)(b_ * NHEAD + h)) * SEQ + s_) * DH + d]) =
                        make_float2(v0, v1);
                }
            }
        }
    }
}

// ---------------------------------------------------------------------------
// 4) Flash attention (fp32, online softmax); epilogue writes bf16 hi/lo split
// ---------------------------------------------------------------------------
__global__ __launch_bounds__(256) void attn_kernel(const float* __restrict__ mask)
{
    __shared__ float Qs[64 * 64];
    __shared__ float KVs[64 * 64];
    __shared__ float Psm[64 * 64];

    const int tid = threadIdx.x;
    const int tx  = tid & 15;
    const int ty  = tid >> 4;
    const int bh  = blockIdx.y;
    const int b   = bh >> 4;
    const int h   = bh & 15;
    const int qt  = blockIdx.x;

    const float* Qg = g_q + ((size_t)bh * SEQ + (size_t)qt * 64) * DH;
    const float* Kg = g_k + (size_t)bh * SEQ * DH;
    const float* Vg = g_v + (size_t)bh * SEQ * DH;
    const float* mk = mask + (size_t)b * SEQ;

    #pragma unroll
    for (int it = 0; it < 4; it++) {
        const int r  = it * 16 + (tid >> 4);
        const int c4 = (tid & 15) * 4;
        *reinterpret_cast<float4*>(&Qs[r * 64 + c4]) =
            *reinterpret_cast<const float4*>(&Qg[(size_t)r * DH + c4]);
    }

    float O[4][4] = {};
    float m_run[4], l_run[4];
    #pragma unroll
    for (int i = 0; i < 4; i++) { m_run[i] = -1e30f; l_run[i] = 0.f; }

    const int qr0 = ty * 4;
    const int dc0 = tx * 4;

    for (int kt = 0; kt < SEQ / 64; kt++) {
        #pragma unroll
        for (int it = 0; it < 4; it++) {
            const int r  = it * 16 + (tid >> 4);
            const int d4 = tid & 15;
            const float4 kv4 = *reinterpret_cast<const float4*>(
                &Kg[((size_t)kt * 64 + r) * DH + d4 * 4]);
            *reinterpret_cast<float4*>(
                &KVs[r * 64 + (((d4 ^ (r >> 2)) & 15) << 2)]) = kv4;
        }
        __syncthreads();

        float sacc[4][4] = {};
        #pragma unroll
        for (int d4 = 0; d4 < 16; d4++) {
            float4 qv[4], kr[4];
            #pragma unroll
            for (int i = 0; i < 4; i++)
                qv[i] = *reinterpret_cast<const float4*>(&Qs[(qr0 + i) * 64 + d4 * 4]);
            #pragma unroll
            for (int j = 0; j < 4; j++)
                kr[j] = *reinterpret_cast<const float4*>(
                    &KVs[(tx * 4 + j) * 64 + (((d4 ^ tx) & 15) << 2)]);
            #pragma unroll
            for (int i = 0; i < 4; i++)
                #pragma unroll
                for (int j = 0; j < 4; j++)
                    sacc[i][j] += qv[i].x * kr[j].x + qv[i].y * kr[j].y +
                                  qv[i].z * kr[j].z + qv[i].w * kr[j].w;
        }

        float mkv[4];
        #pragma unroll
        for (int j = 0; j < 4; j++)
            mkv[j] = __ldg(&mk[kt * 64 + tx * 4 + j]);

        #pragma unroll
        for (int i = 0; i < 4; i++) {
            float sv0 = sacc[i][0] * 0.125f + mkv[0];
            float sv1 = sacc[i][1] * 0.125f + mkv[1];
            float sv2 = sacc[i][2] * 0.125f + mkv[2];
            float sv3 = sacc[i][3] * 0.125f + mkv[3];
            float rm = fmaxf(fmaxf(sv0, sv1), fmaxf(sv2, sv3));
            #pragma unroll
            for (int m = 1; m < 16; m <<= 1)
                rm = fmaxf(rm, __shfl_xor_sync(0xffffffffu, rm, m));
            const float mnew = fmaxf(m_run[i], rm);
            const float corr = __expf(m_run[i] - mnew);
            const float p0 = __expf(sv0 - mnew);
            const float p1 = __expf(sv1 - mnew);
            const float p2 = __expf(sv2 - mnew);
            const float p3 = __expf(sv3 - mnew);
            float rs = p0 + p1 + p2 + p3;
            #pragma unroll
            for (int m = 1; m < 16; m <<= 1)
                rs += __shfl_xor_sync(0xffffffffu, rs, m);
            l_run[i] = l_run[i] * corr + rs;
            m_run[i] = mnew;
            #pragma unroll
            for (int j = 0; j < 4; j++) O[i][j] *= corr;
            *reinterpret_cast<float4*>(&Psm[(qr0 + i) * 64 + (tx << 2)]) =
                make_float4(p0, p1, p2, p3);
        }
        __syncthreads();

        #pragma unroll
        for (int it = 0; it < 4; it++) {
            const int r  = it * 16 + (tid >> 4);
            const int d4 = tid & 15;
            *reinterpret_cast<float4*>(&KVs[r * 64 + d4 * 4]) =
                *reinterpret_cast<const float4*>(&Vg[((size_t)kt * 64 + r) * DH + d4 * 4]);
        }
        __syncthreads();

        #pragma unroll
        for (int k4 = 0; k4 < 16; k4++) {
            float4 pv[4];
            #pragma unroll
            for (int i = 0; i < 4; i++)
                pv[i] = *reinterpret_cast<const float4*>(&Psm[(qr0 + i) * 64 + k4 * 4]);
            const float4 vv0 = *reinterpret_cast<const float4*>(&KVs[(k4 * 4 + 0) * 64 + dc0]);
            const float4 vv1 = *reinterpret_cast<const float4*>(&KVs[(k4 * 4 + 1) * 64 + dc0]);
            const float4 vv2 = *reinterpret_cast<const float4*>(&KVs[(k4 * 4 + 2) * 64 + dc0]);
            const float4 vv3 = *reinterpret_cast<const float4*>(&KVs[(k4 * 4 + 3) * 64 + dc0]);
            #pragma unroll
            for (int i = 0; i < 4; i++) {
                O[i][0] += pv[i].x * vv0.x + pv[i].y * vv1.x + pv[i].z * vv2.x + pv[i].w * vv3.x;
                O[i][1] += pv[i].x * vv0.y + pv[i].y * vv1.y + pv[i].z * vv2.y + pv[i].w * vv3.y;
                O[i][2] += pv[i].x * vv0.z + pv[i].y * vv1.z + pv[i].z * vv2.z + pv[i].w * vv3.z;
                O[i][3] += pv[i].x * vv0.w + pv[i].y * vv1.w + pv[i].z * vv2.w + pv[i].w * vv3.w;
            }
        }
        __syncthreads();
    }

    // epilogue: normalize, split to bf16 hi/lo, write into g_ah/g_al
    #pragma unroll
    for (int i = 0; i < 4; i++) {
        const float inv = 1.0f / l_run[i];
        const int srow = qt * 64 + qr0 + i;
        const size_t off = ((size_t)b * SEQ + srow) * HID + h * DH + dc0;
        float v[4] = { O[i][0] * inv, O[i][1] * inv, O[i][2] * inv, O[i][3] * inv };
        __nv_bfloat16 hh[4], ll[4];
        #pragma unroll
        for (int j = 0; j < 4; j++) {
            hh[j] = __float2bfloat16(v[j]);
            ll[j] = __float2bfloat16(v[j] - __bfloat162float(hh[j]));
        }
        *reinterpret_cast<__nv_bfloat162*>(g_ah + off)     = __halves2bfloat162(hh[0], hh[1]);
        *reinterpret_cast<__nv_bfloat162*>(g_ah + off + 2) = __halves2bfloat162(hh[2], hh[3]);
        *reinterpret_cast<__nv_bfloat162*>(g_al + off)     = __halves2bfloat162(ll[0], ll[1]);
        *reinterpret_cast<__nv_bfloat162*>(g_al + off + 2) = __halves2bfloat162(ll[2], ll[3]);
    }
}

// ---------------------------------------------------------------------------
// kernel_launch
// ---------------------------------------------------------------------------
extern "C" void kernel_launch(void* const* d_in, const int* in_sizes, int n_in,
                              void* d_out, int out_size)
{
    (void)in_sizes; (void)n_in; (void)out_size;
    const float* hidden = (const float*)d_in[0];
    const float* mask   = (const float*)d_in[1];
    const float* gamma  = (const float*)d_in[2];
    const float* beta   = (const float*)d_in[3];
    const float* Wqkv   = (const float*)d_in[4];
    const float* bqkv   = (const float*)d_in[5];
    const float* Wout   = (const float*)d_in[6];
    const float* bout   = (const float*)d_in[7];
    float* out = (float*)d_out;

    cudaFuncSetAttribute(mm_kernel,
                         cudaFuncAttributeMaxDynamicSharedMemorySize, MM_SMEM);

    ln_kernel<<<NTOK, 256>>>(hidden, gamma, beta);
    conv_w<<<dim3(3 * HID / 32, HID / 32), dim3(32, 8)>>>(Wqkv, 0, 3 * HID);
    conv_w<<<dim3(HID / 32, HID / 32), dim3(32, 8)>>>(Wout, 1, HID);
    mm_kernel<<<dim3(3 * HID / 128, NTOK / 128), 256, MM_SMEM>>>(0, bqkv, nullptr, nullptr);
    attn_kernel<<<dim3(SEQ / 64, BATCH * NHEAD), 256>>>(mask);
    mm_kernel<<<dim3(HID / 128, NTOK / 128), 256, MM_SMEM>>>(1, bout, hidden, out);
}

// round 11
// speedup vs baseline: 3.9262x; 2.6729x over previous
#include <cuda_runtime.h>
#include <cuda_bf16.h>
#include <cstdint>

// Problem constants
#define HID   1024
#define BATCH 4
#define SEQ   2048
#define NHEAD 16
#define DH    64
#define NTOK  (BATCH * SEQ)   // 8192

// ---------------------------------------------------------------------------
// Scratch (static __device__ arrays; no allocation anywhere)
// ---------------------------------------------------------------------------
// bf16-split activations (LN output, later attention output) [tok][1024]
__device__ __nv_bfloat16 g_ah[(size_t)NTOK * HID];
__device__ __nv_bfloat16 g_al[(size_t)NTOK * HID];
// bf16-split transposed weights [N][K]
__device__ __nv_bfloat16 g_wqh[(size_t)3 * HID * HID];
__device__ __nv_bfloat16 g_wql[(size_t)3 * HID * HID];
__device__ __nv_bfloat16 g_woh[(size_t)HID * HID];
__device__ __nv_bfloat16 g_wol[(size_t)HID * HID];
// attention operands [b*16+h][s][64]
__device__ __nv_bfloat16 g_qh[(size_t)NTOK * DH * NHEAD / NHEAD * NHEAD]; // = NTOK*HID/16*16
__device__ __nv_bfloat16 g_ql[(size_t)NTOK * DH * NHEAD];
__device__ __nv_bfloat16 g_kh[(size_t)NTOK * DH * NHEAD];
__device__ __nv_bfloat16 g_kl[(size_t)NTOK * DH * NHEAD];
__device__ __nv_bfloat16 g_vh[(size_t)NTOK * DH * NHEAD];

// ---------------------------------------------------------------------------
// Warp-MMA helpers (family-compatible: ldmatrix + mma.sync + cp.async)
// ---------------------------------------------------------------------------
__device__ __forceinline__ uint32_t smem_u32(const void* p) {
    return (uint32_t)__cvta_generic_to_shared(p);
}

__device__ __forceinline__ void cp16(uint32_t dst, const void* src) {
    asm volatile("cp.async.cg.shared.global [%0], [%1], 16;" :: "r"(dst), "l"(src));
}
#define CP_COMMIT() asm volatile("cp.async.commit_group;" ::: "memory")
#define CP_WAIT0()  asm volatile("cp.async.wait_group 0;" ::: "memory")
#define CP_WAIT1()  asm volatile("cp.async.wait_group 1;" ::: "memory")

__device__ __forceinline__ void ldsm_x4(uint32_t* r, uint32_t addr) {
    asm volatile("ldmatrix.sync.aligned.m8n8.x4.shared.b16 {%0,%1,%2,%3}, [%4];"
        : "=r"(r[0]), "=r"(r[1]), "=r"(r[2]), "=r"(r[3]) : "r"(addr));
}
__device__ __forceinline__ void ldsm_x4_t(uint32_t* r, uint32_t addr) {
    asm volatile("ldmatrix.sync.aligned.m8n8.x4.trans.shared.b16 {%0,%1,%2,%3}, [%4];"
        : "=r"(r[0]), "=r"(r[1]), "=r"(r[2]), "=r"(r[3]) : "r"(addr));
}

__device__ __forceinline__ void mma_bf16(float* c, const uint32_t* a, const uint32_t* b) {
    asm volatile(
        "mma.sync.aligned.m16n8k16.row.col.f32.bf16.bf16.f32 "
        "{%0,%1,%2,%3}, {%4,%5,%6,%7}, {%8,%9}, {%0,%1,%2,%3};"
        : "+f"(c[0]), "+f"(c[1]), "+f"(c[2]), "+f"(c[3])
        : "r"(a[0]), "r"(a[1]), "r"(a[2]), "r"(a[3]), "r"(b[0]), "r"(b[1]));
}

__device__ __forceinline__ uint32_t pack_bf16(float lo, float hi) {
    __nv_bfloat162 t = __float22bfloat162_rn(make_float2(lo, hi));
    return *reinterpret_cast<uint32_t*>(&t);
}

// ---------------------------------------------------------------------------
// 1) LayerNorm fused with bf16 hi/lo split -> g_ah / g_al
// ---------------------------------------------------------------------------
__global__ __launch_bounds__(256) void ln_kernel(
    const float* __restrict__ x,
    const float* __restrict__ gamma,
    const float* __restrict__ beta)
{
    const int t   = blockIdx.x;
    const int tid = threadIdx.x;

    const float4 f = reinterpret_cast<const float4*>(x + (size_t)t * HID)[tid];
    float s  = f.x + f.y + f.z + f.w;
    float ss = f.x * f.x + f.y * f.y + f.z * f.z + f.w * f.w;

    #pragma unroll
    for (int m = 16; m; m >>= 1) {
        s  += __shfl_xor_sync(0xffffffffu, s,  m);
        ss += __shfl_xor_sync(0xffffffffu, ss, m);
    }
    __shared__ float red0[8], red1[8];
    const int w = tid >> 5, l = tid & 31;
    if (l == 0) { red0[w] = s; red1[w] = ss; }
    __syncthreads();
    s = 0.f; ss = 0.f;
    #pragma unroll
    for (int i = 0; i < 8; i++) { s += red0[i]; ss += red1[i]; }

    const float mean = s * (1.0f / HID);
    const float var  = ss * (1.0f / HID) - mean * mean;
    const float rstd = rsqrtf(var + 1e-12f);

    const float4 g = reinterpret_cast<const float4*>(gamma)[tid];
    const float4 b = reinterpret_cast<const float4*>(beta)[tid];
    float o[4];
    o[0] = (f.x - mean) * rstd * g.x + b.x;
    o[1] = (f.y - mean) * rstd * g.y + b.y;
    o[2] = (f.z - mean) * rstd * g.z + b.z;
    o[3] = (f.w - mean) * rstd * g.w + b.w;

    const size_t off = (size_t)t * HID + tid * 4;
    __nv_bfloat16 h[4], lo[4];
    #pragma unroll
    for (int i = 0; i < 4; i++) {
        h[i]  = __float2bfloat16(o[i]);
        lo[i] = __float2bfloat16(o[i] - __bfloat162float(h[i]));
    }
    *reinterpret_cast<__nv_bfloat162*>(g_ah + off)     = __halves2bfloat162(h[0], h[1]);
    *reinterpret_cast<__nv_bfloat162*>(g_ah + off + 2) = __halves2bfloat162(h[2], h[3]);
    *reinterpret_cast<__nv_bfloat162*>(g_al + off)     = __halves2bfloat162(lo[0], lo[1]);
    *reinterpret_cast<__nv_bfloat162*>(g_al + off + 2) = __halves2bfloat162(lo[2], lo[3]);
}

// ---------------------------------------------------------------------------
// 2) Transpose + split weights: W [K=1024][Ndim] -> T{h,l} [Ndim][1024]
// ---------------------------------------------------------------------------
__global__ __launch_bounds__(256) void conv_w(const float* __restrict__ W,
                                              int which, int Ndim)
{
    __nv_bfloat16* Th = which ? g_woh : g_wqh;
    __nv_bfloat16* Tl = which ? g_wol : g_wql;

    __shared__ float t[32][33];
    const int n0 = blockIdx.x * 32, k0 = blockIdx.y * 32;
    const int x = threadIdx.x, y = threadIdx.y;

    #pragma unroll
    for (int i = 0; i < 4; i++)
        t[y + i * 8][x] = W[(size_t)(k0 + y + i * 8) * Ndim + n0 + x];
    __syncthreads();

    #pragma unroll
    for (int i = 0; i < 4; i++) {
        const int n = n0 + y + i * 8;
        const int k = k0 + x;
        const float v = t[x][y + i * 8];
        const __nv_bfloat16 h = __float2bfloat16(v);
        Th[(size_t)n * HID + k] = h;
        Tl[(size_t)n * HID + k] = __float2bfloat16(v - __bfloat162float(h));
    }
}

// ---------------------------------------------------------------------------
// 3) Tensor-core GEMM (mma.sync bf16, 3-term split), CTA 128x128, BK=32
//    which: 0 = QKV (emit bf16 q-split/k-split/v), 1 = OUT (bias+resid -> outp)
// ---------------------------------------------------------------------------
#define MM_SMEM 65536

__global__ __launch_bounds__(256) void mm_kernel(
    int which, const float* __restrict__ bias,
    const float* __restrict__ resid, float* __restrict__ outp)
{
    extern __shared__ char smem[];
    const uint32_t sb = smem_u32(smem);
    const int tid  = threadIdx.x;
    const int lane = tid & 31;
    const int wid  = tid >> 5;
    const int wm   = wid >> 2;
    const int wn   = wid & 3;
    const int row0 = blockIdx.y * 128;
    const int col0 = blockIdx.x * 128;

    const __nv_bfloat16* Ah = g_ah + (size_t)row0 * HID;
    const __nv_bfloat16* Al = g_al + (size_t)row0 * HID;
    const __nv_bfloat16* Bh = (which ? g_woh : g_wqh) + (size_t)col0 * HID;
    const __nv_bfloat16* Bl = (which ? g_wol : g_wql) + (size_t)col0 * HID;

    float C[4][4][4];
    #pragma unroll
    for (int i = 0; i < 4; i++)
        #pragma unroll
        for (int j = 0; j < 4; j++)
            #pragma unroll
            for (int k = 0; k < 4; k++) C[i][j][k] = 0.f;

    auto load_slab = [&](int kt, int buf) {
        const uint32_t base = sb + (uint32_t)buf * 32768u;
        #pragma unroll
        for (int it = 0; it < 8; it++) {
            const int c   = it * 256 + tid;
            const int arr = c >> 9;
            const int cc  = c & 511;
            const int r   = cc >> 2;
            const int j   = cc & 3;
            const uint32_t soff = (uint32_t)(arr * 8192 + r * 64 +
                                             ((j ^ ((r >> 1) & 3)) << 4));
            const __nv_bfloat16* src =
                (arr == 0 ? Ah : arr == 1 ? Al : arr == 2 ? Bh : Bl)
                + (size_t)r * HID + kt * 32 + j * 8;
            cp16(base + soff, src);
        }
    };

    auto compute = [&](int buf) {
        const uint32_t base = sb + (uint32_t)buf * 32768u;
        #pragma unroll
        for (int ks = 0; ks < 2; ks++) {
            uint32_t ah[4][4], al[4][4], bh[4][2], bl[4][2];
            #pragma unroll
            for (int mt = 0; mt < 4; mt++) {
                const int r  = wm * 64 + mt * 16 + (lane & 15);
                const int jc = ks * 2 + (lane >> 4);
                const uint32_t addr = base + (uint32_t)(r * 64 +
                                        ((jc ^ ((r >> 1) & 3)) << 4));
                ldsm_x4(ah[mt], addr);
                ldsm_x4(al[mt], addr + 8192);
            }
            #pragma unroll
            for (int p = 0; p < 2; p++) {
                const int r  = wn * 32 + p * 16 + (lane & 7) + ((lane >> 4) << 3);
                const int jc = ks * 2 + ((lane >> 3) & 1);
                const uint32_t addr = base + 16384u + (uint32_t)(r * 64 +
                                        ((jc ^ ((r >> 1) & 3)) << 4));
                uint32_t t4[4];
                ldsm_x4(t4, addr);
                bh[2 * p][0] = t4[0]; bh[2 * p][1] = t4[1];
                bh[2 * p + 1][0] = t4[2]; bh[2 * p + 1][1] = t4[3];
                ldsm_x4(t4, addr + 8192);
                bl[2 * p][0] = t4[0]; bl[2 * p][1] = t4[1];
                bl[2 * p + 1][0] = t4[2]; bl[2 * p + 1][1] = t4[3];
            }
            #pragma unroll
            for (int mt = 0; mt < 4; mt++)
                #pragma unroll
                for (int nt = 0; nt < 4; nt++) {
                    mma_bf16(C[mt][nt], ah[mt], bh[nt]);
                    mma_bf16(C[mt][nt], ah[mt], bl[nt]);
                    mma_bf16(C[mt][nt], al[mt], bh[nt]);
                }
        }
    };

    load_slab(0, 0);
    CP_COMMIT();
    for (int kt = 0; kt < 32; kt++) {
        const int cur = kt & 1;
        if (kt + 1 < 32) {
            load_slab(kt + 1, cur ^ 1);
            CP_COMMIT();
            CP_WAIT1();
        } else {
            CP_WAIT0();
        }
        __syncthreads();
        compute(cur);
        __syncthreads();
    }

    // ---- epilogue ----
    const int r_lane = lane >> 2;
    const int c_lane = (lane & 3) * 2;

    #pragma unroll
    for (int mt = 0; mt < 4; mt++) {
        #pragma unroll
        for (int half = 0; half < 2; half++) {
            const int m  = row0 + wm * 64 + mt * 16 + r_lane + half * 8;
            const int b_ = m >> 11;
            const int s_ = m & 2047;
            #pragma unroll
            for (int nt = 0; nt < 4; nt++) {
                const int n = col0 + wn * 32 + nt * 8 + c_lane;
                float v0 = C[mt][nt][half * 2 + 0] + bias[n];
                float v1 = C[mt][nt][half * 2 + 1] + bias[n + 1];
                if (which) {
                    const size_t off = (size_t)m * HID + n;
                    const float2 rr = *reinterpret_cast<const float2*>(resid + off);
                    *reinterpret_cast<float2*>(outp + off) =
                        make_float2(v0 + rr.x, v1 + rr.y);
                } else {
                    const int part = n >> 10;
                    const int h = (n & 1023) >> 6;
                    const int d = n & 63;
                    const size_t off =
                        (((size_t)(b_ * NHEAD + h)) * SEQ + s_) * DH + d;
                    if (part == 0) {
                        // q: fold 1/sqrt(DH)=0.125, split hi/lo
                        v0 *= 0.125f; v1 *= 0.125f;
                        __nv_bfloat16 h0 = __float2bfloat16(v0);
                        __nv_bfloat16 h1 = __float2bfloat16(v1);
                        *reinterpret_cast<__nv_bfloat162*>(g_qh + off) =
                            __halves2bfloat162(h0, h1);
                        *reinterpret_cast<__nv_bfloat162*>(g_ql + off) =
                            __halves2bfloat162(
                                __float2bfloat16(v0 - __bfloat162float(h0)),
                                __float2bfloat16(v1 - __bfloat162float(h1)));
                    } else if (part == 1) {
                        __nv_bfloat16 h0 = __float2bfloat16(v0);
                        __nv_bfloat16 h1 = __float2bfloat16(v1);
                        *reinterpret_cast<__nv_bfloat162*>(g_kh + off) =
                            __halves2bfloat162(h0, h1);
                        *reinterpret_cast<__nv_bfloat162*>(g_kl + off) =
                            __halves2bfloat162(
                                __float2bfloat16(v0 - __bfloat162float(h0)),
                                __float2bfloat16(v1 - __bfloat162float(h1)));
                    } else {
                        *reinterpret_cast<__nv_bfloat162*>(g_vh + off) =
                            __halves2bfloat162(__float2bfloat16(v0),
                                               __float2bfloat16(v1));
                    }
                }
            }
        }
    }
}

// ---------------------------------------------------------------------------
// 4) Tensor-core flash attention.
//    Grid (16 q-tiles, 64 bh), 256 threads = 8 warps, warp owns 16 q-rows.
//    q-tile 128, kv-tile 64. QK^T uses hi/lo split x3 mma; softmax in regs;
//    PV single bf16. Output -> g_ah/g_al (bf16 split) for the OUT GEMM.
// ---------------------------------------------------------------------------
#define AQ_L   16384
#define ABUF   32768
#define ABUFS  25856
#define AK_L   8192
#define AV     16384
#define AMSK   25600
#define AT_SMEM (ABUF + 2 * ABUFS)   // 84480

__global__ __launch_bounds__(256) void attn_kernel(const float* __restrict__ mask)
{
    extern __shared__ char smem[];
    const uint32_t sb = smem_u32(smem);
    const int tid  = threadIdx.x;
    const int lane = tid & 31;
    const int wid  = tid >> 5;
    const int bh   = blockIdx.y;
    const int b    = bh >> 4;
    const int h    = bh & 15;
    const int qt   = blockIdx.x;

    const __nv_bfloat16* Qh = g_qh + ((size_t)bh * SEQ + (size_t)qt * 128) * DH;
    const __nv_bfloat16* Ql = g_ql + ((size_t)bh * SEQ + (size_t)qt * 128) * DH;
    const __nv_bfloat16* Kh = g_kh + (size_t)bh * SEQ * DH;
    const __nv_bfloat16* Kl = g_kl + (size_t)bh * SEQ * DH;
    const __nv_bfloat16* Vv = g_vh + (size_t)bh * SEQ * DH;
    const float* mk = mask + (size_t)b * SEQ;

    // ---- load Q tile (128 rows x 64, hi+lo): 2048 16B chunks ----
    #pragma unroll
    for (int it = 0; it < 8; it++) {
        const int c   = it * 256 + tid;
        const int arr = c >> 10;
        const int cc  = c & 1023;
        const int r   = cc >> 3, j = cc & 7;
        const uint32_t soff = (uint32_t)((arr ? AQ_L : 0) + r * 128 +
                                         ((j ^ (r & 7)) << 4));
        cp16(sb + soff, (arr ? Ql : Qh) + (size_t)r * DH + j * 8);
    }

    auto load_kv = [&](int kt, int buf) {
        const uint32_t base = sb + ABUF + (uint32_t)buf * ABUFS;
        #pragma unroll
        for (int it = 0; it < 7; it++) {
            const int c = it * 256 + tid;
            if (c < 1536) {
                const int arr = c >> 9;     // 0 KH, 1 KL, 2 V
                const int cc  = c & 511;
                const int r   = cc >> 3, j = cc & 7;
                if (arr < 2) {
                    const uint32_t soff = (uint32_t)((arr ? AK_L : 0) + r * 128 +
                                                     ((j ^ (r & 7)) << 4));
                    cp16(base + soff,
                         (arr ? Kl : Kh) + ((size_t)kt * 64 + r) * DH + j * 8);
                } else {
                    cp16(base + AV + (uint32_t)(r * 144 + j * 16),
                         Vv + ((size_t)kt * 64 + r) * DH + j * 8);
                }
            } else if (c < 1552) {
                const int j = c - 1536;
                cp16(base + AMSK + (uint32_t)(j * 16), mk + kt * 64 + j * 4);
            }
        }
    };

    float O[8][4];
    #pragma unroll
    for (int i = 0; i < 8; i++)
        #pragma unroll
        for (int j = 0; j < 4; j++) O[i][j] = 0.f;
    float m_run[2] = {-1e30f, -1e30f};
    float l_run[2] = {0.f, 0.f};

    load_kv(0, 0);
    CP_COMMIT();

    for (int kt = 0; kt < SEQ / 64; kt++) {
        const int cur = kt & 1;
        if (kt + 1 < SEQ / 64) {
            load_kv(kt + 1, cur ^ 1);
            CP_COMMIT();
            CP_WAIT1();
        } else {
            CP_WAIT0();
        }
        __syncthreads();

        const uint32_t kbase = sb + ABUF + (uint32_t)cur * ABUFS;

        // ---- S = Q' @ K^T  (3-term split) ----
        float C[8][4];
        #pragma unroll
        for (int i = 0; i < 8; i++)
            #pragma unroll
            for (int j = 0; j < 4; j++) C[i][j] = 0.f;

        #pragma unroll
        for (int kd = 0; kd < 4; kd++) {
            uint32_t ah[4], al[4];
            {
                const int r  = wid * 16 + (lane & 15);
                const int jc = kd * 2 + (lane >> 4);
                const uint32_t addr = sb + (uint32_t)(r * 128 +
                                        ((jc ^ (r & 7)) << 4));
                ldsm_x4(ah, addr);
                ldsm_x4(al, addr + AQ_L);
            }
            #pragma unroll
            for (int p = 0; p < 4; p++) {
                const int r  = p * 16 + (lane & 7) + ((lane >> 4) << 3);
                const int jc = kd * 2 + ((lane >> 3) & 1);
                const uint32_t addr = kbase + (uint32_t)(r * 128 +
                                        ((jc ^ (r & 7)) << 4));
                uint32_t th[4], tl[4];
                ldsm_x4(th, addr);
                ldsm_x4(tl, addr + AK_L);
                mma_bf16(C[2 * p],     ah, th);
                mma_bf16(C[2 * p],     ah, tl);
                mma_bf16(C[2 * p],     al, th);
                mma_bf16(C[2 * p + 1], ah, th + 2);
                mma_bf16(C[2 * p + 1], ah, tl + 2);
                mma_bf16(C[2 * p + 1], al, th + 2);
            }
        }

        // ---- online softmax (rows g = lane>>2 and g+8) ----
        const float* msk = reinterpret_cast<const float*>(
            smem + ABUF + (size_t)cur * ABUFS + AMSK);
        const int c0 = (lane & 3) * 2;

        float mloc0 = -1e30f, mloc1 = -1e30f;
        #pragma unroll
        for (int nt = 0; nt < 8; nt++) {
            const float mv0 = msk[nt * 8 + c0];
            const float mv1 = msk[nt * 8 + c0 + 1];
            C[nt][0] += mv0; C[nt][1] += mv1;
            C[nt][2] += mv0; C[nt][3] += mv1;
            mloc0 = fmaxf(mloc0, fmaxf(C[nt][0], C[nt][1]));
            mloc1 = fmaxf(mloc1, fmaxf(C[nt][2], C[nt][3]));
        }
        mloc0 = fmaxf(mloc0, __shfl_xor_sync(0xffffffffu, mloc0, 1));
        mloc0 = fmaxf(mloc0, __shfl_xor_sync(0xffffffffu, mloc0, 2));
        mloc1 = fmaxf(mloc1, __shfl_xor_sync(0xffffffffu, mloc1, 1));
        mloc1 = fmaxf(mloc1, __shfl_xor_sync(0xffffffffu, mloc1, 2));

        const float mnew0 = fmaxf(m_run[0], mloc0);
        const float mnew1 = fmaxf(m_run[1], mloc1);
        const float corr0 = __expf(m_run[0] - mnew0);
        const float corr1 = __expf(m_run[1] - mnew1);

        float ls0 = 0.f, ls1 = 0.f;
        #pragma unroll
        for (int nt = 0; nt < 8; nt++) {
            C[nt][0] = __expf(C[nt][0] - mnew0);
            C[nt][1] = __expf(C[nt][1] - mnew0);
            C[nt][2] = __expf(C[nt][2] - mnew1);
            C[nt][3] = __expf(C[nt][3] - mnew1);
            ls0 += C[nt][0] + C[nt][1];
            ls1 += C[nt][2] + C[nt][3];
        }
        ls0 += __shfl_xor_sync(0xffffffffu, ls0, 1);
        ls0 += __shfl_xor_sync(0xffffffffu, ls0, 2);
        ls1 += __shfl_xor_sync(0xffffffffu, ls1, 1);
        ls1 += __shfl_xor_sync(0xffffffffu, ls1, 2);

        l_run[0] = l_run[0] * corr0 + ls0;
        l_run[1] = l_run[1] * corr1 + ls1;
        m_run[0] = mnew0;
        m_run[1] = mnew1;

        #pragma unroll
        for (int nt = 0; nt < 8; nt++) {
            O[nt][0] *= corr0; O[nt][1] *= corr0;
            O[nt][2] *= corr1; O[nt][3] *= corr1;
        }

        // ---- pack P (C-frag -> A-frag identity) ----
        uint32_t pa[4][4];
        #pragma unroll
        for (int kc = 0; kc < 4; kc++) {
            pa[kc][0] = pack_bf16(C[2 * kc][0],     C[2 * kc][1]);
            pa[kc][1] = pack_bf16(C[2 * kc][2],     C[2 * kc][3]);
            pa[kc][2] = pack_bf16(C[2 * kc + 1][0], C[2 * kc + 1][1]);
            pa[kc][3] = pack_bf16(C[2 * kc + 1][2], C[2 * kc + 1][3]);
        }

        // ---- O += P @ V ----
        #pragma unroll
        for (int kc = 0; kc < 4; kc++) {
            #pragma unroll
            for (int np = 0; np < 4; np++) {
                const int r = kc * 16 + (lane & 7) + (((lane >> 3) & 1) << 3);
                const int jc = 2 * np + (lane >> 4);
                const uint32_t addr = kbase + AV + (uint32_t)(r * 144 + jc * 16);
                uint32_t t4[4];
                ldsm_x4_t(t4, addr);
                mma_bf16(O[2 * np],     pa[kc], t4);
                mma_bf16(O[2 * np + 1], pa[kc], t4 + 2);
            }
        }
        __syncthreads();
    }

    // ---- epilogue: normalize, split, write g_ah/g_al [b][s][h*64+d] ----
    const float inv0 = 1.0f / l_run[0];
    const float inv1 = 1.0f / l_run[1];
    const int g  = lane >> 2;
    const int s0 = qt * 128 + wid * 16 + g;
    const int c0 = (lane & 3) * 2;

    #pragma unroll
    for (int nt = 0; nt < 8; nt++) {
        const int d = h * DH + nt * 8 + c0;
        {
            const size_t off = ((size_t)b * SEQ + s0) * HID + d;
            const float v0 = O[nt][0] * inv0, v1 = O[nt][1] * inv0;
            const __nv_bfloat16 h0 = __float2bfloat16(v0);
            const __nv_bfloat16 h1 = __float2bfloat16(v1);
            *reinterpret_cast<__nv_bfloat162*>(g_ah + off) = __halves2bfloat162(h0, h1);
            *reinterpret_cast<__nv_bfloat162*>(g_al + off) = __halves2bfloat162(
                __float2bfloat16(v0 - __bfloat162float(h0)),
                __float2bfloat16(v1 - __bfloat162float(h1)));
        }
        {
            const size_t off = ((size_t)b * SEQ + s0 + 8) * HID + d;
            const float v0 = O[nt][2] * inv1, v1 = O[nt][3] * inv1;
            const __nv_bfloat16 h0 = __float2bfloat16(v0);
            const __nv_bfloat16 h1 = __float2bfloat16(v1);
            *reinterpret_cast<__nv_bfloat162*>(g_ah + off) = __halves2bfloat162(h0, h1);
            *reinterpret_cast<__nv_bfloat162*>(g_al + off) = __halves2bfloat162(
                __float2bfloat16(v0 - __bfloat162float(h0)),
                __float2bfloat16(v1 - __bfloat162float(h1)));
        }
    }
}

// ---------------------------------------------------------------------------
// kernel_launch
// ---------------------------------------------------------------------------
extern "C" void kernel_launch(void* const* d_in, const int* in_sizes, int n_in,
                              void* d_out, int out_size)
{
    (void)in_sizes; (void)n_in; (void)out_size;
    const float* hidden = (const float*)d_in[0];
    const float* mask   = (const float*)d_in[1];
    const float* gamma  = (const float*)d_in[2];
    const float* beta   = (const float*)d_in[3];
    const float* Wqkv   = (const float*)d_in[4];
    const float* bqkv   = (const float*)d_in[5];
    const float* Wout   = (const float*)d_in[6];
    const float* bout   = (const float*)d_in[7];
    float* out = (float*)d_out;

    cudaFuncSetAttribute(mm_kernel,
                         cudaFuncAttributeMaxDynamicSharedMemorySize, MM_SMEM);
    cudaFuncSetAttribute(attn_kernel,
                         cudaFuncAttributeMaxDynamicSharedMemorySize, AT_SMEM);

    ln_kernel<<<NTOK, 256>>>(hidden, gamma, beta);
    conv_w<<<dim3(3 * HID / 32, HID / 32), dim3(32, 8)>>>(Wqkv, 0, 3 * HID);
    conv_w<<<dim3(HID / 32, HID / 32), dim3(32, 8)>>>(Wout, 1, HID);
    mm_kernel<<<dim3(3 * HID / 128, NTOK / 128), 256, MM_SMEM>>>(0, bqkv, nullptr, nullptr);
    attn_kernel<<<dim3(SEQ / 128, BATCH * NHEAD), 256, AT_SMEM>>>(mask);
    mm_kernel<<<dim3(HID / 128, NTOK / 128), 256, MM_SMEM>>>(1, bout, hidden, out);
}

// round 12
// speedup vs baseline: 3.9264x; 1.0001x over previous
#include <cuda_runtime.h>
#include <cuda_bf16.h>
#include <cstdint>

// Problem constants
#define HID   1024
#define BATCH 4
#define SEQ   2048
#define NHEAD 16
#define DH    64
#define NTOK  (BATCH * SEQ)   // 8192

// ---------------------------------------------------------------------------
// Scratch (static __device__ arrays; no allocation anywhere)
// ---------------------------------------------------------------------------
// bf16-split activations (LN output, later attention output) [tok][1024]
__device__ __nv_bfloat16 g_ah[(size_t)NTOK * HID];
__device__ __nv_bfloat16 g_al[(size_t)NTOK * HID];
// bf16-split transposed weights [N][K]
__device__ __nv_bfloat16 g_wqh[(size_t)3 * HID * HID];
__device__ __nv_bfloat16 g_wql[(size_t)3 * HID * HID];
__device__ __nv_bfloat16 g_woh[(size_t)HID * HID];
__device__ __nv_bfloat16 g_wol[(size_t)HID * HID];
// attention operands [b*16+h][s][64]
__device__ __nv_bfloat16 g_qh[(size_t)NTOK * DH * NHEAD / NHEAD * NHEAD]; // = NTOK*HID/16*16
__device__ __nv_bfloat16 g_ql[(size_t)NTOK * DH * NHEAD];
__device__ __nv_bfloat16 g_kh[(size_t)NTOK * DH * NHEAD];
__device__ __nv_bfloat16 g_kl[(size_t)NTOK * DH * NHEAD];
__device__ __nv_bfloat16 g_vh[(size_t)NTOK * DH * NHEAD];

// ---------------------------------------------------------------------------
// Warp-MMA helpers (family-compatible: ldmatrix + mma.sync + cp.async)
// ---------------------------------------------------------------------------
__device__ __forceinline__ uint32_t smem_u32(const void* p) {
    return (uint32_t)__cvta_generic_to_shared(p);
}

__device__ __forceinline__ void cp16(uint32_t dst, const void* src) {
    asm volatile("cp.async.cg.shared.global [%0], [%1], 16;" :: "r"(dst), "l"(src));
}
#define CP_COMMIT() asm volatile("cp.async.commit_group;" ::: "memory")
#define CP_WAIT0()  asm volatile("cp.async.wait_group 0;" ::: "memory")
#define CP_WAIT1()  asm volatile("cp.async.wait_group 1;" ::: "memory")

__device__ __forceinline__ void ldsm_x4(uint32_t* r, uint32_t addr) {
    asm volatile("ldmatrix.sync.aligned.m8n8.x4.shared.b16 {%0,%1,%2,%3}, [%4];"
        : "=r"(r[0]), "=r"(r[1]), "=r"(r[2]), "=r"(r[3]) : "r"(addr));
}
__device__ __forceinline__ void ldsm_x4_t(uint32_t* r, uint32_t addr) {
    asm volatile("ldmatrix.sync.aligned.m8n8.x4.trans.shared.b16 {%0,%1,%2,%3}, [%4];"
        : "=r"(r[0]), "=r"(r[1]), "=r"(r[2]), "=r"(r[3]) : "r"(addr));
}

__device__ __forceinline__ void mma_bf16(float* c, const uint32_t* a, const uint32_t* b) {
    asm volatile(
        "mma.sync.aligned.m16n8k16.row.col.f32.bf16.bf16.f32 "
        "{%0,%1,%2,%3}, {%4,%5,%6,%7}, {%8,%9}, {%0,%1,%2,%3};"
        : "+f"(c[0]), "+f"(c[1]), "+f"(c[2]), "+f"(c[3])
        : "r"(a[0]), "r"(a[1]), "r"(a[2]), "r"(a[3]), "r"(b[0]), "r"(b[1]));
}

__device__ __forceinline__ uint32_t pack_bf16(float lo, float hi) {
    __nv_bfloat162 t = __float22bfloat162_rn(make_float2(lo, hi));
    return *reinterpret_cast<uint32_t*>(&t);
}

// ---------------------------------------------------------------------------
// 1) LayerNorm fused with bf16 hi/lo split -> g_ah / g_al
// ---------------------------------------------------------------------------
__global__ __launch_bounds__(256) void ln_kernel(
    const float* __restrict__ x,
    const float* __restrict__ gamma,
    const float* __restrict__ beta)
{
    const int t   = blockIdx.x;
    const int tid = threadIdx.x;

    const float4 f = reinterpret_cast<const float4*>(x + (size_t)t * HID)[tid];
    float s  = f.x + f.y + f.z + f.w;
    float ss = f.x * f.x + f.y * f.y + f.z * f.z + f.w * f.w;

    #pragma unroll
    for (int m = 16; m; m >>= 1) {
        s  += __shfl_xor_sync(0xffffffffu, s,  m);
        ss += __shfl_xor_sync(0xffffffffu, ss, m);
    }
    __shared__ float red0[8], red1[8];
    const int w = tid >> 5, l = tid & 31;
    if (l == 0) { red0[w] = s; red1[w] = ss; }
    __syncthreads();
    s = 0.f; ss = 0.f;
    #pragma unroll
    for (int i = 0; i < 8; i++) { s += red0[i]; ss += red1[i]; }

    const float mean = s * (1.0f / HID);
    const float var  = ss * (1.0f / HID) - mean * mean;
    const float rstd = rsqrtf(var + 1e-12f);

    const float4 g = reinterpret_cast<const float4*>(gamma)[tid];
    const float4 b = reinterpret_cast<const float4*>(beta)[tid];
    float o[4];
    o[0] = (f.x - mean) * rstd * g.x + b.x;
    o[1] = (f.y - mean) * rstd * g.y + b.y;
    o[2] = (f.z - mean) * rstd * g.z + b.z;
    o[3] = (f.w - mean) * rstd * g.w + b.w;

    const size_t off = (size_t)t * HID + tid * 4;
    __nv_bfloat16 h[4], lo[4];
    #pragma unroll
    for (int i = 0; i < 4; i++) {
        h[i]  = __float2bfloat16(o[i]);
        lo[i] = __float2bfloat16(o[i] - __bfloat162float(h[i]));
    }
    *reinterpret_cast<__nv_bfloat162*>(g_ah + off)     = __halves2bfloat162(h[0], h[1]);
    *reinterpret_cast<__nv_bfloat162*>(g_ah + off + 2) = __halves2bfloat162(h[2], h[3]);
    *reinterpret_cast<__nv_bfloat162*>(g_al + off)     = __halves2bfloat162(lo[0], lo[1]);
    *reinterpret_cast<__nv_bfloat162*>(g_al + off + 2) = __halves2bfloat162(lo[2], lo[3]);
}

// ---------------------------------------------------------------------------
// 2) Transpose + split weights: W [K=1024][Ndim] -> T{h,l} [Ndim][1024]
// ---------------------------------------------------------------------------
__global__ __launch_bounds__(256) void conv_w(const float* __restrict__ W,
                                              int which, int Ndim)
{
    __nv_bfloat16* Th = which ? g_woh : g_wqh;
    __nv_bfloat16* Tl = which ? g_wol : g_wql;

    __shared__ float t[32][33];
    const int n0 = blockIdx.x * 32, k0 = blockIdx.y * 32;
    const int x = threadIdx.x, y = threadIdx.y;

    #pragma unroll
    for (int i = 0; i < 4; i++)
        t[y + i * 8][x] = W[(size_t)(k0 + y + i * 8) * Ndim + n0 + x];
    __syncthreads();

    #pragma unroll
    for (int i = 0; i < 4; i++) {
        const int n = n0 + y + i * 8;
        const int k = k0 + x;
        const float v = t[x][y + i * 8];
        const __nv_bfloat16 h = __float2bfloat16(v);
        Th[(size_t)n * HID + k] = h;
        Tl[(size_t)n * HID + k] = __float2bfloat16(v - __bfloat162float(h));
    }
}

// ---------------------------------------------------------------------------
// 3) Tensor-core GEMM (mma.sync bf16, 3-term split), CTA 128x128, BK=32
//    which: 0 = QKV (emit bf16 q-split/k-split/v), 1 = OUT (bias+resid -> outp)
// ---------------------------------------------------------------------------
#define MM_SMEM 65536

__global__ __launch_bounds__(256) void mm_kernel(
    int which, const float* __restrict__ bias,
    const float* __restrict__ resid, float* __restrict__ outp)
{
    extern __shared__ char smem[];
    const uint32_t sb = smem_u32(smem);
    const int tid  = threadIdx.x;
    const int lane = tid & 31;
    const int wid  = tid >> 5;
    const int wm   = wid >> 2;
    const int wn   = wid & 3;
    const int row0 = blockIdx.y * 128;
    const int col0 = blockIdx.x * 128;

    const __nv_bfloat16* Ah = g_ah + (size_t)row0 * HID;
    const __nv_bfloat16* Al = g_al + (size_t)row0 * HID;
    const __nv_bfloat16* Bh = (which ? g_woh : g_wqh) + (size_t)col0 * HID;
    const __nv_bfloat16* Bl = (which ? g_wol : g_wql) + (size_t)col0 * HID;

    float C[4][4][4];
    #pragma unroll
    for (int i = 0; i < 4; i++)
        #pragma unroll
        for (int j = 0; j < 4; j++)
            #pragma unroll
            for (int k = 0; k < 4; k++) C[i][j][k] = 0.f;

    auto load_slab = [&](int kt, int buf) {
        const uint32_t base = sb + (uint32_t)buf * 32768u;
        #pragma unroll
        for (int it = 0; it < 8; it++) {
            const int c   = it * 256 + tid;
            const int arr = c >> 9;
            const int cc  = c & 511;
            const int r   = cc >> 2;
            const int j   = cc & 3;
            const uint32_t soff = (uint32_t)(arr * 8192 + r * 64 +
                                             ((j ^ ((r >> 1) & 3)) << 4));
            const __nv_bfloat16* src =
                (arr == 0 ? Ah : arr == 1 ? Al : arr == 2 ? Bh : Bl)
                + (size_t)r * HID + kt * 32 + j * 8;
            cp16(base + soff, src);
        }
    };

    auto compute = [&](int buf) {
        const uint32_t base = sb + (uint32_t)buf * 32768u;
        #pragma unroll
        for (int ks = 0; ks < 2; ks++) {
            uint32_t ah[4][4], al[4][4], bh[4][2], bl[4][2];
            #pragma unroll
            for (int mt = 0; mt < 4; mt++) {
                const int r  = wm * 64 + mt * 16 + (lane & 15);
                const int jc = ks * 2 + (lane >> 4);
                const uint32_t addr = base + (uint32_t)(r * 64 +
                                        ((jc ^ ((r >> 1) & 3)) << 4));
                ldsm_x4(ah[mt], addr);
                ldsm_x4(al[mt], addr + 8192);
            }
            #pragma unroll
            for (int p = 0; p < 2; p++) {
                const int r  = wn * 32 + p * 16 + (lane & 7) + ((lane >> 4) << 3);
                const int jc = ks * 2 + ((lane >> 3) & 1);
                const uint32_t addr = base + 16384u + (uint32_t)(r * 64 +
                                        ((jc ^ ((r >> 1) & 3)) << 4));
                uint32_t t4[4];
                ldsm_x4(t4, addr);
                bh[2 * p][0] = t4[0]; bh[2 * p][1] = t4[1];
                bh[2 * p + 1][0] = t4[2]; bh[2 * p + 1][1] = t4[3];
                ldsm_x4(t4, addr + 8192);
                bl[2 * p][0] = t4[0]; bl[2 * p][1] = t4[1];
                bl[2 * p + 1][0] = t4[2]; bl[2 * p + 1][1] = t4[3];
            }
            #pragma unroll
            for (int mt = 0; mt < 4; mt++)
                #pragma unroll
                for (int nt = 0; nt < 4; nt++) {
                    mma_bf16(C[mt][nt], ah[mt], bh[nt]);
                    mma_bf16(C[mt][nt], ah[mt], bl[nt]);
                    mma_bf16(C[mt][nt], al[mt], bh[nt]);
                }
        }
    };

    load_slab(0, 0);
    CP_COMMIT();
    for (int kt = 0; kt < 32; kt++) {
        const int cur = kt & 1;
        if (kt + 1 < 32) {
            load_slab(kt + 1, cur ^ 1);
            CP_COMMIT();
            CP_WAIT1();
        } else {
            CP_WAIT0();
        }
        __syncthreads();
        compute(cur);
        __syncthreads();
    }

    // ---- epilogue ----
    const int r_lane = lane >> 2;
    const int c_lane = (lane & 3) * 2;

    #pragma unroll
    for (int mt = 0; mt < 4; mt++) {
        #pragma unroll
        for (int half = 0; half < 2; half++) {
            const int m  = row0 + wm * 64 + mt * 16 + r_lane + half * 8;
            const int b_ = m >> 11;
            const int s_ = m & 2047;
            #pragma unroll
            for (int nt = 0; nt < 4; nt++) {
                const int n = col0 + wn * 32 + nt * 8 + c_lane;
                float v0 = C[mt][nt][half * 2 + 0] + bias[n];
                float v1 = C[mt][nt][half * 2 + 1] + bias[n + 1];
                if (which) {
                    const size_t off = (size_t)m * HID + n;
                    const float2 rr = *reinterpret_cast<const float2*>(resid + off);
                    *reinterpret_cast<float2*>(outp + off) =
                        make_float2(v0 + rr.x, v1 + rr.y);
                } else {
                    const int part = n >> 10;
                    const int h = (n & 1023) >> 6;
                    const int d = n & 63;
                    const size_t off =
                        (((size_t)(b_ * NHEAD + h)) * SEQ + s_) * DH + d;
                    if (part == 0) {
                        // q: fold 1/sqrt(DH)=0.125, split hi/lo
                        v0 *= 0.125f; v1 *= 0.125f;
                        __nv_bfloat16 h0 = __float2bfloat16(v0);
                        __nv_bfloat16 h1 = __float2bfloat16(v1);
                        *reinterpret_cast<__nv_bfloat162*>(g_qh + off) =
                            __halves2bfloat162(h0, h1);
                        *reinterpret_cast<__nv_bfloat162*>(g_ql + off) =
                            __halves2bfloat162(
                                __float2bfloat16(v0 - __bfloat162float(h0)),
                                __float2bfloat16(v1 - __bfloat162float(h1)));
                    } else if (part == 1) {
                        __nv_bfloat16 h0 = __float2bfloat16(v0);
                        __nv_bfloat16 h1 = __float2bfloat16(v1);
                        *reinterpret_cast<__nv_bfloat162*>(g_kh + off) =
                            __halves2bfloat162(h0, h1);
                        *reinterpret_cast<__nv_bfloat162*>(g_kl + off) =
                            __halves2bfloat162(
                                __float2bfloat16(v0 - __bfloat162float(h0)),
                                __float2bfloat16(v1 - __bfloat162float(h1)));
                    } else {
                        *reinterpret_cast<__nv_bfloat162*>(g_vh + off) =
                            __halves2bfloat162(__float2bfloat16(v0),
                                               __float2bfloat16(v1));
                    }
                }
            }
        }
    }
}

// ---------------------------------------------------------------------------
// 4) Tensor-core flash attention.
//    Grid (16 q-tiles, 64 bh), 256 threads = 8 warps, warp owns 16 q-rows.
//    q-tile 128, kv-tile 64. QK^T uses hi/lo split x3 mma; softmax in regs;
//    PV single bf16. Output -> g_ah/g_al (bf16 split) for the OUT GEMM.
// ---------------------------------------------------------------------------
#define AQ_L   16384
#define ABUF   32768
#define ABUFS  25856
#define AK_L   8192
#define AV     16384
#define AMSK   25600
#define AT_SMEM (ABUF + 2 * ABUFS)   // 84480

__global__ __launch_bounds__(256) void attn_kernel(const float* __restrict__ mask)
{
    extern __shared__ char smem[];
    const uint32_t sb = smem_u32(smem);
    const int tid  = threadIdx.x;
    const int lane = tid & 31;
    const int wid  = tid >> 5;
    const int bh   = blockIdx.y;
    const int b    = bh >> 4;
    const int h    = bh & 15;
    const int qt   = blockIdx.x;

    const __nv_bfloat16* Qh = g_qh + ((size_t)bh * SEQ + (size_t)qt * 128) * DH;
    const __nv_bfloat16* Ql = g_ql + ((size_t)bh * SEQ + (size_t)qt * 128) * DH;
    const __nv_bfloat16* Kh = g_kh + (size_t)bh * SEQ * DH;
    const __nv_bfloat16* Kl = g_kl + (size_t)bh * SEQ * DH;
    const __nv_bfloat16* Vv = g_vh + (size_t)bh * SEQ * DH;
    const float* mk = mask + (size_t)b * SEQ;

    // ---- load Q tile (128 rows x 64, hi+lo): 2048 16B chunks ----
    #pragma unroll
    for (int it = 0; it < 8; it++) {
        const int c   = it * 256 + tid;
        const int arr = c >> 10;
        const int cc  = c & 1023;
        const int r   = cc >> 3, j = cc & 7;
        const uint32_t soff = (uint32_t)((arr ? AQ_L : 0) + r * 128 +
                                         ((j ^ (r & 7)) << 4));
        cp16(sb + soff, (arr ? Ql : Qh) + (size_t)r * DH + j * 8);
    }

    auto load_kv = [&](int kt, int buf) {
        const uint32_t base = sb + ABUF + (uint32_t)buf * ABUFS;
        #pragma unroll
        for (int it = 0; it < 7; it++) {
            const int c = it * 256 + tid;
            if (c < 1536) {
                const int arr = c >> 9;     // 0 KH, 1 KL, 2 V
                const int cc  = c & 511;
                const int r   = cc >> 3, j = cc & 7;
                if (arr < 2) {
                    const uint32_t soff = (uint32_t)((arr ? AK_L : 0) + r * 128 +
                                                     ((j ^ (r & 7)) << 4));
                    cp16(base + soff,
                         (arr ? Kl : Kh) + ((size_t)kt * 64 + r) * DH + j * 8);
                } else {
                    cp16(base + AV + (uint32_t)(r * 144 + j * 16),
                         Vv + ((size_t)kt * 64 + r) * DH + j * 8);
                }
            } else if (c < 1552) {
                const int j = c - 1536;
                cp16(base + AMSK + (uint32_t)(j * 16), mk + kt * 64 + j * 4);
            }
        }
    };

    float O[8][4];
    #pragma unroll
    for (int i = 0; i < 8; i++)
        #pragma unroll
        for (int j = 0; j < 4; j++) O[i][j] = 0.f;
    float m_run[2] = {-1e30f, -1e30f};
    float l_run[2] = {0.f, 0.f};

    load_kv(0, 0);
    CP_COMMIT();

    for (int kt = 0; kt < SEQ / 64; kt++) {
        const int cur = kt & 1;
        if (kt + 1 < SEQ / 64) {
            load_kv(kt + 1, cur ^ 1);
            CP_COMMIT();
            CP_WAIT1();
        } else {
            CP_WAIT0();
        }
        __syncthreads();

        const uint32_t kbase = sb + ABUF + (uint32_t)cur * ABUFS;

        // ---- S = Q' @ K^T  (3-term split) ----
        float C[8][4];
        #pragma unroll
        for (int i = 0; i < 8; i++)
            #pragma unroll
            for (int j = 0; j < 4; j++) C[i][j] = 0.f;

        #pragma unroll
        for (int kd = 0; kd < 4; kd++) {
            uint32_t ah[4], al[4];
            {
                const int r  = wid * 16 + (lane & 15);
                const int jc = kd * 2 + (lane >> 4);
                const uint32_t addr = sb + (uint32_t)(r * 128 +
                                        ((jc ^ (r & 7)) << 4));
                ldsm_x4(ah, addr);
                ldsm_x4(al, addr + AQ_L);
            }
            #pragma unroll
            for (int p = 0; p < 4; p++) {
                const int r  = p * 16 + (lane & 7) + ((lane >> 4) << 3);
                const int jc = kd * 2 + ((lane >> 3) & 1);
                const uint32_t addr = kbase + (uint32_t)(r * 128 +
                                        ((jc ^ (r & 7)) << 4));
                uint32_t th[4], tl[4];
                ldsm_x4(th, addr);
                ldsm_x4(tl, addr + AK_L);
                mma_bf16(C[2 * p],     ah, th);
                mma_bf16(C[2 * p],     ah, tl);
                mma_bf16(C[2 * p],     al, th);
                mma_bf16(C[2 * p + 1], ah, th + 2);
                mma_bf16(C[2 * p + 1], ah, tl + 2);
                mma_bf16(C[2 * p + 1], al, th + 2);
            }
        }

        // ---- online softmax (rows g = lane>>2 and g+8) ----
        const float* msk = reinterpret_cast<const float*>(
            smem + ABUF + (size_t)cur * ABUFS + AMSK);
        const int c0 = (lane & 3) * 2;

        float mloc0 = -1e30f, mloc1 = -1e30f;
        #pragma unroll
        for (int nt = 0; nt < 8; nt++) {
            const float mv0 = msk[nt * 8 + c0];
            const float mv1 = msk[nt * 8 + c0 + 1];
            C[nt][0] += mv0; C[nt][1] += mv1;
            C[nt][2] += mv0; C[nt][3] += mv1;
            mloc0 = fmaxf(mloc0, fmaxf(C[nt][0], C[nt][1]));
            mloc1 = fmaxf(mloc1, fmaxf(C[nt][2], C[nt][3]));
        }
        mloc0 = fmaxf(mloc0, __shfl_xor_sync(0xffffffffu, mloc0, 1));
        mloc0 = fmaxf(mloc0, __shfl_xor_sync(0xffffffffu, mloc0, 2));
        mloc1 = fmaxf(mloc1, __shfl_xor_sync(0xffffffffu, mloc1, 1));
        mloc1 = fmaxf(mloc1, __shfl_xor_sync(0xffffffffu, mloc1, 2));

        const float mnew0 = fmaxf(m_run[0], mloc0);
        const float mnew1 = fmaxf(m_run[1], mloc1);
        const float corr0 = __expf(m_run[0] - mnew0);
        const float corr1 = __expf(m_run[1] - mnew1);

        float ls0 = 0.f, ls1 = 0.f;
        #pragma unroll
        for (int nt = 0; nt < 8; nt++) {
            C[nt][0] = __expf(C[nt][0] - mnew0);
            C[nt][1] = __expf(C[nt][1] - mnew0);
            C[nt][2] = __expf(C[nt][2] - mnew1);
            C[nt][3] = __expf(C[nt][3] - mnew1);
            ls0 += C[nt][0] + C[nt][1];
            ls1 += C[nt][2] + C[nt][3];
        }
        ls0 += __shfl_xor_sync(0xffffffffu, ls0, 1);
        ls0 += __shfl_xor_sync(0xffffffffu, ls0, 2);
        ls1 += __shfl_xor_sync(0xffffffffu, ls1, 1);
        ls1 += __shfl_xor_sync(0xffffffffu, ls1, 2);

        l_run[0] = l_run[0] * corr0 + ls0;
        l_run[1] = l_run[1] * corr1 + ls1;
        m_run[0] = mnew0;
        m_run[1] = mnew1;

        #pragma unroll
        for (int nt = 0; nt < 8; nt++) {
            O[nt][0] *= corr0; O[nt][1] *= corr0;
            O[nt][2] *= corr1; O[nt][3] *= corr1;
        }

        // ---- pack P (C-frag -> A-frag identity) ----
        uint32_t pa[4][4];
        #pragma unroll
        for (int kc = 0; kc < 4; kc++) {
            pa[kc][0] = pack_bf16(C[2 * kc][0],     C[2 * kc][1]);
            pa[kc][1] = pack_bf16(C[2 * kc][2],     C[2 * kc][3]);
            pa[kc][2] = pack_bf16(C[2 * kc + 1][0], C[2 * kc + 1][1]);
            pa[kc][3] = pack_bf16(C[2 * kc + 1][2], C[2 * kc + 1][3]);
        }

        // ---- O += P @ V ----
        #pragma unroll
        for (int kc = 0; kc < 4; kc++) {
            #pragma unroll
            for (int np = 0; np < 4; np++) {
                const int r = kc * 16 + (lane & 7) + (((lane >> 3) & 1) << 3);
                const int jc = 2 * np + (lane >> 4);
                const uint32_t addr = kbase + AV + (uint32_t)(r * 144 + jc * 16);
                uint32_t t4[4];
                ldsm_x4_t(t4, addr);
                mma_bf16(O[2 * np],     pa[kc], t4);
                mma_bf16(O[2 * np + 1], pa[kc], t4 + 2);
            }
        }
        __syncthreads();
    }

    // ---- epilogue: normalize, split, write g_ah/g_al [b][s][h*64+d] ----
    const float inv0 = 1.0f / l_run[0];
    const float inv1 = 1.0f / l_run[1];
    const int g  = lane >> 2;
    const int s0 = qt * 128 + wid * 16 + g;
    const int c0 = (lane & 3) * 2;

    #pragma unroll
    for (int nt = 0; nt < 8; nt++) {
        const int d = h * DH + nt * 8 + c0;
        {
            const size_t off = ((size_t)b * SEQ + s0) * HID + d;
            const float v0 = O[nt][0] * inv0, v1 = O[nt][1] * inv0;
            const __nv_bfloat16 h0 = __float2bfloat16(v0);
            const __nv_bfloat16 h1 = __float2bfloat16(v1);
            *reinterpret_cast<__nv_bfloat162*>(g_ah + off) = __halves2bfloat162(h0, h1);
            *reinterpret_cast<__nv_bfloat162*>(g_al + off) = __halves2bfloat162(
                __float2bfloat16(v0 - __bfloat162float(h0)),
                __float2bfloat16(v1 - __bfloat162float(h1)));
        }
        {
            const size_t off = ((size_t)b * SEQ + s0 + 8) * HID + d;
            const float v0 = O[nt][2] * inv1, v1 = O[nt][3] * inv1;
            const __nv_bfloat16 h0 = __float2bfloat16(v0);
            const __nv_bfloat16 h1 = __float2bfloat16(v1);
            *reinterpret_cast<__nv_bfloat162*>(g_ah + off) = __halves2bfloat162(h0, h1);
            *reinterpret_cast<__nv_bfloat162*>(g_al + off) = __halves2bfloat162(
                __float2bfloat16(v0 - __bfloat162float(h0)),
                __float2bfloat16(v1 - __bfloat162float(h1)));
        }
    }
}

// ---------------------------------------------------------------------------
// kernel_launch
// ---------------------------------------------------------------------------
extern "C" void kernel_launch(void* const* d_in, const int* in_sizes, int n_in,
                              void* d_out, int out_size)
{
    (void)in_sizes; (void)n_in; (void)out_size;
    const float* hidden = (const float*)d_in[0];
    const float* mask   = (const float*)d_in[1];
    const float* gamma  = (const float*)d_in[2];
    const float* beta   = (const float*)d_in[3];
    const float* Wqkv   = (const float*)d_in[4];
    const float* bqkv   = (const float*)d_in[5];
    const float* Wout   = (const float*)d_in[6];
    const float* bout   = (const float*)d_in[7];
    float* out = (float*)d_out;

    cudaFuncSetAttribute(mm_kernel,
                         cudaFuncAttributeMaxDynamicSharedMemorySize, MM_SMEM);
    cudaFuncSetAttribute(attn_kernel,
                         cudaFuncAttributeMaxDynamicSharedMemorySize, AT_SMEM);

    ln_kernel<<<NTOK, 256>>>(hidden, gamma, beta);
    conv_w<<<dim3(3 * HID / 32, HID / 32), dim3(32, 8)>>>(Wqkv, 0, 3 * HID);
    conv_w<<<dim3(HID / 32, HID / 32), dim3(32, 8)>>>(Wout, 1, HID);
    mm_kernel<<<dim3(3 * HID / 128, NTOK / 128), 256, MM_SMEM>>>(0, bqkv, nullptr, nullptr);
    attn_kernel<<<dim3(SEQ / 128, BATCH * NHEAD), 256, AT_SMEM>>>(mask);
    mm_kernel<<<dim3(HID / 128, NTOK / 128), 256, MM_SMEM>>>(1, bout, hidden, out);
}

// round 13
// speedup vs baseline: 3.9335x; 1.0018x over previous
#include <cuda_runtime.h>
#include <cuda_bf16.h>
#include <cstdint>

// Problem constants
#define HID   1024
#define BATCH 4
#define SEQ   2048
#define NHEAD 16
#define DH    64
#define NTOK  (BATCH * SEQ)   // 8192

// ---------------------------------------------------------------------------
// Scratch (static __device__ arrays; no allocation anywhere)
// ---------------------------------------------------------------------------
// bf16-split activations (LN output, later attention output) [tok][1024]
__device__ __nv_bfloat16 g_ah[(size_t)NTOK * HID];
__device__ __nv_bfloat16 g_al[(size_t)NTOK * HID];
// bf16-split transposed weights [N][K]
__device__ __nv_bfloat16 g_wqh[(size_t)3 * HID * HID];
__device__ __nv_bfloat16 g_wql[(size_t)3 * HID * HID];
__device__ __nv_bfloat16 g_woh[(size_t)HID * HID];
__device__ __nv_bfloat16 g_wol[(size_t)HID * HID];
// attention operands [b*16+h][s][64]
__device__ __nv_bfloat16 g_qh[(size_t)NTOK * DH * NHEAD / NHEAD * NHEAD]; // = NTOK*HID/16*16
__device__ __nv_bfloat16 g_ql[(size_t)NTOK * DH * NHEAD];
__device__ __nv_bfloat16 g_kh[(size_t)NTOK * DH * NHEAD];
__device__ __nv_bfloat16 g_kl[(size_t)NTOK * DH * NHEAD];
__device__ __nv_bfloat16 g_vh[(size_t)NTOK * DH * NHEAD];

// ---------------------------------------------------------------------------
// Warp-MMA helpers (family-compatible: ldmatrix + mma.sync + cp.async)
// ---------------------------------------------------------------------------
__device__ __forceinline__ uint32_t smem_u32(const void* p) {
    return (uint32_t)__cvta_generic_to_shared(p);
}

__device__ __forceinline__ void cp16(uint32_t dst, const void* src) {
    asm volatile("cp.async.cg.shared.global [%0], [%1], 16;" :: "r"(dst), "l"(src));
}
#define CP_COMMIT() asm volatile("cp.async.commit_group;" ::: "memory")
#define CP_WAIT0()  asm volatile("cp.async.wait_group 0;" ::: "memory")
#define CP_WAIT1()  asm volatile("cp.async.wait_group 1;" ::: "memory")

__device__ __forceinline__ void ldsm_x4(uint32_t* r, uint32_t addr) {
    asm volatile("ldmatrix.sync.aligned.m8n8.x4.shared.b16 {%0,%1,%2,%3}, [%4];"
        : "=r"(r[0]), "=r"(r[1]), "=r"(r[2]), "=r"(r[3]) : "r"(addr));
}
__device__ __forceinline__ void ldsm_x4_t(uint32_t* r, uint32_t addr) {
    asm volatile("ldmatrix.sync.aligned.m8n8.x4.trans.shared.b16 {%0,%1,%2,%3}, [%4];"
        : "=r"(r[0]), "=r"(r[1]), "=r"(r[2]), "=r"(r[3]) : "r"(addr));
}

__device__ __forceinline__ void mma_bf16(float* c, const uint32_t* a, const uint32_t* b) {
    asm volatile(
        "mma.sync.aligned.m16n8k16.row.col.f32.bf16.bf16.f32 "
        "{%0,%1,%2,%3}, {%4,%5,%6,%7}, {%8,%9}, {%0,%1,%2,%3};"
        : "+f"(c[0]), "+f"(c[1]), "+f"(c[2]), "+f"(c[3])
        : "r"(a[0]), "r"(a[1]), "r"(a[2]), "r"(a[3]), "r"(b[0]), "r"(b[1]));
}

__device__ __forceinline__ uint32_t pack_bf16(float lo, float hi) {
    __nv_bfloat162 t = __float22bfloat162_rn(make_float2(lo, hi));
    return *reinterpret_cast<uint32_t*>(&t);
}

// ---------------------------------------------------------------------------
// 1) LayerNorm fused with bf16 hi/lo split -> g_ah / g_al
// ---------------------------------------------------------------------------
__global__ __launch_bounds__(256) void ln_kernel(
    const float* __restrict__ x,
    const float* __restrict__ gamma,
    const float* __restrict__ beta)
{
    const int t   = blockIdx.x;
    const int tid = threadIdx.x;

    const float4 f = reinterpret_cast<const float4*>(x + (size_t)t * HID)[tid];
    float s  = f.x + f.y + f.z + f.w;
    float ss = f.x * f.x + f.y * f.y + f.z * f.z + f.w * f.w;

    #pragma unroll
    for (int m = 16; m; m >>= 1) {
        s  += __shfl_xor_sync(0xffffffffu, s,  m);
        ss += __shfl_xor_sync(0xffffffffu, ss, m);
    }
    __shared__ float red0[8], red1[8];
    const int w = tid >> 5, l = tid & 31;
    if (l == 0) { red0[w] = s; red1[w] = ss; }
    __syncthreads();
    s = 0.f; ss = 0.f;
    #pragma unroll
    for (int i = 0; i < 8; i++) { s += red0[i]; ss += red1[i]; }

    const float mean = s * (1.0f / HID);
    const float var  = ss * (1.0f / HID) - mean * mean;
    const float rstd = rsqrtf(var + 1e-12f);

    const float4 g = reinterpret_cast<const float4*>(gamma)[tid];
    const float4 b = reinterpret_cast<const float4*>(beta)[tid];
    float o[4];
    o[0] = (f.x - mean) * rstd * g.x + b.x;
    o[1] = (f.y - mean) * rstd * g.y + b.y;
    o[2] = (f.z - mean) * rstd * g.z + b.z;
    o[3] = (f.w - mean) * rstd * g.w + b.w;

    const size_t off = (size_t)t * HID + tid * 4;
    __nv_bfloat16 h[4], lo[4];
    #pragma unroll
    for (int i = 0; i < 4; i++) {
        h[i]  = __float2bfloat16(o[i]);
        lo[i] = __float2bfloat16(o[i] - __bfloat162float(h[i]));
    }
    *reinterpret_cast<__nv_bfloat162*>(g_ah + off)     = __halves2bfloat162(h[0], h[1]);
    *reinterpret_cast<__nv_bfloat162*>(g_ah + off + 2) = __halves2bfloat162(h[2], h[3]);
    *reinterpret_cast<__nv_bfloat162*>(g_al + off)     = __halves2bfloat162(lo[0], lo[1]);
    *reinterpret_cast<__nv_bfloat162*>(g_al + off + 2) = __halves2bfloat162(lo[2], lo[3]);
}

// ---------------------------------------------------------------------------
// 2) Transpose + split weights: W [K=1024][Ndim] -> T{h,l} [Ndim][1024]
// ---------------------------------------------------------------------------
__global__ __launch_bounds__(256) void conv_w(const float* __restrict__ W,
                                              int which, int Ndim)
{
    __nv_bfloat16* Th = which ? g_woh : g_wqh;
    __nv_bfloat16* Tl = which ? g_wol : g_wql;

    __shared__ float t[32][33];
    const int n0 = blockIdx.x * 32, k0 = blockIdx.y * 32;
    const int x = threadIdx.x, y = threadIdx.y;

    #pragma unroll
    for (int i = 0; i < 4; i++)
        t[y + i * 8][x] = W[(size_t)(k0 + y + i * 8) * Ndim + n0 + x];
    __syncthreads();

    #pragma unroll
    for (int i = 0; i < 4; i++) {
        const int n = n0 + y + i * 8;
        const int k = k0 + x;
        const float v = t[x][y + i * 8];
        const __nv_bfloat16 h = __float2bfloat16(v);
        Th[(size_t)n * HID + k] = h;
        Tl[(size_t)n * HID + k] = __float2bfloat16(v - __bfloat162float(h));
    }
}

// ---------------------------------------------------------------------------
// 3) Tensor-core GEMM (mma.sync bf16, 3-term split), CTA 128x128, BK=32
//    which: 0 = QKV (emit bf16 q-split/k-split/v), 1 = OUT (bias+resid -> outp)
// ---------------------------------------------------------------------------
#define MM_SMEM 65536

__global__ __launch_bounds__(256) void mm_kernel(
    int which, const float* __restrict__ bias,
    const float* __restrict__ resid, float* __restrict__ outp)
{
    extern __shared__ char smem[];
    const uint32_t sb = smem_u32(smem);
    const int tid  = threadIdx.x;
    const int lane = tid & 31;
    const int wid  = tid >> 5;
    const int wm   = wid >> 2;
    const int wn   = wid & 3;
    const int row0 = blockIdx.y * 128;
    const int col0 = blockIdx.x * 128;

    const __nv_bfloat16* Ah = g_ah + (size_t)row0 * HID;
    const __nv_bfloat16* Al = g_al + (size_t)row0 * HID;
    const __nv_bfloat16* Bh = (which ? g_woh : g_wqh) + (size_t)col0 * HID;
    const __nv_bfloat16* Bl = (which ? g_wol : g_wql) + (size_t)col0 * HID;

    float C[4][4][4];
    #pragma unroll
    for (int i = 0; i < 4; i++)
        #pragma unroll
        for (int j = 0; j < 4; j++)
            #pragma unroll
            for (int k = 0; k < 4; k++) C[i][j][k] = 0.f;

    auto load_slab = [&](int kt, int buf) {
        const uint32_t base = sb + (uint32_t)buf * 32768u;
        #pragma unroll
        for (int it = 0; it < 8; it++) {
            const int c   = it * 256 + tid;
            const int arr = c >> 9;
            const int cc  = c & 511;
            const int r   = cc >> 2;
            const int j   = cc & 3;
            const uint32_t soff = (uint32_t)(arr * 8192 + r * 64 +
                                             ((j ^ ((r >> 1) & 3)) << 4));
            const __nv_bfloat16* src =
                (arr == 0 ? Ah : arr == 1 ? Al : arr == 2 ? Bh : Bl)
                + (size_t)r * HID + kt * 32 + j * 8;
            cp16(base + soff, src);
        }
    };

    auto compute = [&](int buf) {
        const uint32_t base = sb + (uint32_t)buf * 32768u;
        #pragma unroll
        for (int ks = 0; ks < 2; ks++) {
            uint32_t ah[4][4], al[4][4], bh[4][2], bl[4][2];
            #pragma unroll
            for (int mt = 0; mt < 4; mt++) {
                const int r  = wm * 64 + mt * 16 + (lane & 15);
                const int jc = ks * 2 + (lane >> 4);
                const uint32_t addr = base + (uint32_t)(r * 64 +
                                        ((jc ^ ((r >> 1) & 3)) << 4));
                ldsm_x4(ah[mt], addr);
                ldsm_x4(al[mt], addr + 8192);
            }
            #pragma unroll
            for (int p = 0; p < 2; p++) {
                const int r  = wn * 32 + p * 16 + (lane & 7) + ((lane >> 4) << 3);
                const int jc = ks * 2 + ((lane >> 3) & 1);
                const uint32_t addr = base + 16384u + (uint32_t)(r * 64 +
                                        ((jc ^ ((r >> 1) & 3)) << 4));
                uint32_t t4[4];
                ldsm_x4(t4, addr);
                bh[2 * p][0] = t4[0]; bh[2 * p][1] = t4[1];
                bh[2 * p + 1][0] = t4[2]; bh[2 * p + 1][1] = t4[3];
                ldsm_x4(t4, addr + 8192);
                bl[2 * p][0] = t4[0]; bl[2 * p][1] = t4[1];
                bl[2 * p + 1][0] = t4[2]; bl[2 * p + 1][1] = t4[3];
            }
            #pragma unroll
            for (int mt = 0; mt < 4; mt++)
                #pragma unroll
                for (int nt = 0; nt < 4; nt++) {
                    mma_bf16(C[mt][nt], ah[mt], bh[nt]);
                    mma_bf16(C[mt][nt], ah[mt], bl[nt]);
                    mma_bf16(C[mt][nt], al[mt], bh[nt]);
                }
        }
    };

    load_slab(0, 0);
    CP_COMMIT();
    for (int kt = 0; kt < 32; kt++) {
        const int cur = kt & 1;
        if (kt + 1 < 32) {
            load_slab(kt + 1, cur ^ 1);
            CP_COMMIT();
            CP_WAIT1();
        } else {
            CP_WAIT0();
        }
        __syncthreads();
        compute(cur);
        __syncthreads();
    }

    // ---- epilogue ----
    const int r_lane = lane >> 2;
    const int c_lane = (lane & 3) * 2;

    #pragma unroll
    for (int mt = 0; mt < 4; mt++) {
        #pragma unroll
        for (int half = 0; half < 2; half++) {
            const int m  = row0 + wm * 64 + mt * 16 + r_lane + half * 8;
            const int b_ = m >> 11;
            const int s_ = m & 2047;
            #pragma unroll
            for (int nt = 0; nt < 4; nt++) {
                const int n = col0 + wn * 32 + nt * 8 + c_lane;
                float v0 = C[mt][nt][half * 2 + 0] + bias[n];
                float v1 = C[mt][nt][half * 2 + 1] + bias[n + 1];
                if (which) {
                    const size_t off = (size_t)m * HID + n;
                    const float2 rr = *reinterpret_cast<const float2*>(resid + off);
                    *reinterpret_cast<float2*>(outp + off) =
                        make_float2(v0 + rr.x, v1 + rr.y);
                } else {
                    const int part = n >> 10;
                    const int h = (n & 1023) >> 6;
                    const int d = n & 63;
                    const size_t off =
                        (((size_t)(b_ * NHEAD + h)) * SEQ + s_) * DH + d;
                    if (part == 0) {
                        // q: fold 1/sqrt(DH)=0.125, split hi/lo
                        v0 *= 0.125f; v1 *= 0.125f;
                        __nv_bfloat16 h0 = __float2bfloat16(v0);
                        __nv_bfloat16 h1 = __float2bfloat16(v1);
                        *reinterpret_cast<__nv_bfloat162*>(g_qh + off) =
                            __halves2bfloat162(h0, h1);
                        *reinterpret_cast<__nv_bfloat162*>(g_ql + off) =
                            __halves2bfloat162(
                                __float2bfloat16(v0 - __bfloat162float(h0)),
                                __float2bfloat16(v1 - __bfloat162float(h1)));
                    } else if (part == 1) {
                        __nv_bfloat16 h0 = __float2bfloat16(v0);
                        __nv_bfloat16 h1 = __float2bfloat16(v1);
                        *reinterpret_cast<__nv_bfloat162*>(g_kh + off) =
                            __halves2bfloat162(h0, h1);
                        *reinterpret_cast<__nv_bfloat162*>(g_kl + off) =
                            __halves2bfloat162(
                                __float2bfloat16(v0 - __bfloat162float(h0)),
                                __float2bfloat16(v1 - __bfloat162float(h1)));
                    } else {
                        *reinterpret_cast<__nv_bfloat162*>(g_vh + off) =
                            __halves2bfloat162(__float2bfloat16(v0),
                                               __float2bfloat16(v1));
                    }
                }
            }
        }
    }
}

// ---------------------------------------------------------------------------
// 4) Tensor-core flash attention.
//    Grid (16 q-tiles, 64 bh), 256 threads = 8 warps, warp owns 16 q-rows.
//    q-tile 128, kv-tile 64. QK^T uses hi/lo split x3 mma; softmax in regs;
//    PV single bf16. Output -> g_ah/g_al (bf16 split) for the OUT GEMM.
// ---------------------------------------------------------------------------
#define AQ_L   16384
#define ABUF   32768
#define ABUFS  25856
#define AK_L   8192
#define AV     16384
#define AMSK   25600
#define AT_SMEM (ABUF + 2 * ABUFS)   // 84480

__global__ __launch_bounds__(256) void attn_kernel(const float* __restrict__ mask)
{
    extern __shared__ char smem[];
    const uint32_t sb = smem_u32(smem);
    const int tid  = threadIdx.x;
    const int lane = tid & 31;
    const int wid  = tid >> 5;
    const int bh   = blockIdx.y;
    const int b    = bh >> 4;
    const int h    = bh & 15;
    const int qt   = blockIdx.x;

    const __nv_bfloat16* Qh = g_qh + ((size_t)bh * SEQ + (size_t)qt * 128) * DH;
    const __nv_bfloat16* Ql = g_ql + ((size_t)bh * SEQ + (size_t)qt * 128) * DH;
    const __nv_bfloat16* Kh = g_kh + (size_t)bh * SEQ * DH;
    const __nv_bfloat16* Kl = g_kl + (size_t)bh * SEQ * DH;
    const __nv_bfloat16* Vv = g_vh + (size_t)bh * SEQ * DH;
    const float* mk = mask + (size_t)b * SEQ;

    // ---- load Q tile (128 rows x 64, hi+lo): 2048 16B chunks ----
    #pragma unroll
    for (int it = 0; it < 8; it++) {
        const int c   = it * 256 + tid;
        const int arr = c >> 10;
        const int cc  = c & 1023;
        const int r   = cc >> 3, j = cc & 7;
        const uint32_t soff = (uint32_t)((arr ? AQ_L : 0) + r * 128 +
                                         ((j ^ (r & 7)) << 4));
        cp16(sb + soff, (arr ? Ql : Qh) + (size_t)r * DH + j * 8);
    }

    auto load_kv = [&](int kt, int buf) {
        const uint32_t base = sb + ABUF + (uint32_t)buf * ABUFS;
        #pragma unroll
        for (int it = 0; it < 7; it++) {
            const int c = it * 256 + tid;
            if (c < 1536) {
                const int arr = c >> 9;     // 0 KH, 1 KL, 2 V
                const int cc  = c & 511;
                const int r   = cc >> 3, j = cc & 7;
                if (arr < 2) {
                    const uint32_t soff = (uint32_t)((arr ? AK_L : 0) + r * 128 +
                                                     ((j ^ (r & 7)) << 4));
                    cp16(base + soff,
                         (arr ? Kl : Kh) + ((size_t)kt * 64 + r) * DH + j * 8);
                } else {
                    cp16(base + AV + (uint32_t)(r * 144 + j * 16),
                         Vv + ((size_t)kt * 64 + r) * DH + j * 8);
                }
            } else if (c < 1552) {
                const int j = c - 1536;
                cp16(base + AMSK + (uint32_t)(j * 16), mk + kt * 64 + j * 4);
            }
        }
    };

    float O[8][4];
    #pragma unroll
    for (int i = 0; i < 8; i++)
        #pragma unroll
        for (int j = 0; j < 4; j++) O[i][j] = 0.f;
    float m_run[2] = {-1e30f, -1e30f};
    float l_run[2] = {0.f, 0.f};

    load_kv(0, 0);
    CP_COMMIT();

    for (int kt = 0; kt < SEQ / 64; kt++) {
        const int cur = kt & 1;
        if (kt + 1 < SEQ / 64) {
            load_kv(kt + 1, cur ^ 1);
            CP_COMMIT();
            CP_WAIT1();
        } else {
            CP_WAIT0();
        }
        __syncthreads();

        const uint32_t kbase = sb + ABUF + (uint32_t)cur * ABUFS;

        // ---- S = Q' @ K^T  (3-term split) ----
        float C[8][4];
        #pragma unroll
        for (int i = 0; i < 8; i++)
            #pragma unroll
            for (int j = 0; j < 4; j++) C[i][j] = 0.f;

        #pragma unroll
        for (int kd = 0; kd < 4; kd++) {
            uint32_t ah[4], al[4];
            {
                const int r  = wid * 16 + (lane & 15);
                const int jc = kd * 2 + (lane >> 4);
                const uint32_t addr = sb + (uint32_t)(r * 128 +
                                        ((jc ^ (r & 7)) << 4));
                ldsm_x4(ah, addr);
                ldsm_x4(al, addr + AQ_L);
            }
            #pragma unroll
            for (int p = 0; p < 4; p++) {
                const int r  = p * 16 + (lane & 7) + ((lane >> 4) << 3);
                const int jc = kd * 2 + ((lane >> 3) & 1);
                const uint32_t addr = kbase + (uint32_t)(r * 128 +
                                        ((jc ^ (r & 7)) << 4));
                uint32_t th[4], tl[4];
                ldsm_x4(th, addr);
                ldsm_x4(tl, addr + AK_L);
                mma_bf16(C[2 * p],     ah, th);
                mma_bf16(C[2 * p],     ah, tl);
                mma_bf16(C[2 * p],     al, th);
                mma_bf16(C[2 * p + 1], ah, th + 2);
                mma_bf16(C[2 * p + 1], ah, tl + 2);
                mma_bf16(C[2 * p + 1], al, th + 2);
            }
        }

        // ---- online softmax (rows g = lane>>2 and g+8) ----
        const float* msk = reinterpret_cast<const float*>(
            smem + ABUF + (size_t)cur * ABUFS + AMSK);
        const int c0 = (lane & 3) * 2;

        float mloc0 = -1e30f, mloc1 = -1e30f;
        #pragma unroll
        for (int nt = 0; nt < 8; nt++) {
            const float mv0 = msk[nt * 8 + c0];
            const float mv1 = msk[nt * 8 + c0 + 1];
            C[nt][0] += mv0; C[nt][1] += mv1;
            C[nt][2] += mv0; C[nt][3] += mv1;
            mloc0 = fmaxf(mloc0, fmaxf(C[nt][0], C[nt][1]));
            mloc1 = fmaxf(mloc1, fmaxf(C[nt][2], C[nt][3]));
        }
        mloc0 = fmaxf(mloc0, __shfl_xor_sync(0xffffffffu, mloc0, 1));
        mloc0 = fmaxf(mloc0, __shfl_xor_sync(0xffffffffu, mloc0, 2));
        mloc1 = fmaxf(mloc1, __shfl_xor_sync(0xffffffffu, mloc1, 1));
        mloc1 = fmaxf(mloc1, __shfl_xor_sync(0xffffffffu, mloc1, 2));

        const float mnew0 = fmaxf(m_run[0], mloc0);
        const float mnew1 = fmaxf(m_run[1], mloc1);
        const float corr0 = __expf(m_run[0] - mnew0);
        const float corr1 = __expf(m_run[1] - mnew1);

        float ls0 = 0.f, ls1 = 0.f;
        #pragma unroll
        for (int nt = 0; nt < 8; nt++) {
            C[nt][0] = __expf(C[nt][0] - mnew0);
            C[nt][1] = __expf(C[nt][1] - mnew0);
            C[nt][2] = __expf(C[nt][2] - mnew1);
            C[nt][3] = __expf(C[nt][3] - mnew1);
            ls0 += C[nt][0] + C[nt][1];
            ls1 += C[nt][2] + C[nt][3];
        }
        ls0 += __shfl_xor_sync(0xffffffffu, ls0, 1);
        ls0 += __shfl_xor_sync(0xffffffffu, ls0, 2);
        ls1 += __shfl_xor_sync(0xffffffffu, ls1, 1);
        ls1 += __shfl_xor_sync(0xffffffffu, ls1, 2);

        l_run[0] = l_run[0] * corr0 + ls0;
        l_run[1] = l_run[1] * corr1 + ls1;
        m_run[0] = mnew0;
        m_run[1] = mnew1;

        #pragma unroll
        for (int nt = 0; nt < 8; nt++) {
            O[nt][0] *= corr0; O[nt][1] *= corr0;
            O[nt][2] *= corr1; O[nt][3] *= corr1;
        }

        // ---- pack P (C-frag -> A-frag identity) ----
        uint32_t pa[4][4];
        #pragma unroll
        for (int kc = 0; kc < 4; kc++) {
            pa[kc][0] = pack_bf16(C[2 * kc][0],     C[2 * kc][1]);
            pa[kc][1] = pack_bf16(C[2 * kc][2],     C[2 * kc][3]);
            pa[kc][2] = pack_bf16(C[2 * kc + 1][0], C[2 * kc + 1][1]);
            pa[kc][3] = pack_bf16(C[2 * kc + 1][2], C[2 * kc + 1][3]);
        }

        // ---- O += P @ V ----
        #pragma unroll
        for (int kc = 0; kc < 4; kc++) {
            #pragma unroll
            for (int np = 0; np < 4; np++) {
                const int r = kc * 16 + (lane & 7) + (((lane >> 3) & 1) << 3);
                const int jc = 2 * np + (lane >> 4);
                const uint32_t addr = kbase + AV + (uint32_t)(r * 144 + jc * 16);
                uint32_t t4[4];
                ldsm_x4_t(t4, addr);
                mma_bf16(O[2 * np],     pa[kc], t4);
                mma_bf16(O[2 * np + 1], pa[kc], t4 + 2);
            }
        }
        __syncthreads();
    }

    // ---- epilogue: normalize, split, write g_ah/g_al [b][s][h*64+d] ----
    const float inv0 = 1.0f / l_run[0];
    const float inv1 = 1.0f / l_run[1];
    const int g  = lane >> 2;
    const int s0 = qt * 128 + wid * 16 + g;
    const int c0 = (lane & 3) * 2;

    #pragma unroll
    for (int nt = 0; nt < 8; nt++) {
        const int d = h * DH + nt * 8 + c0;
        {
            const size_t off = ((size_t)b * SEQ + s0) * HID + d;
            const float v0 = O[nt][0] * inv0, v1 = O[nt][1] * inv0;
            const __nv_bfloat16 h0 = __float2bfloat16(v0);
            const __nv_bfloat16 h1 = __float2bfloat16(v1);
            *reinterpret_cast<__nv_bfloat162*>(g_ah + off) = __halves2bfloat162(h0, h1);
            *reinterpret_cast<__nv_bfloat162*>(g_al + off) = __halves2bfloat162(
                __float2bfloat16(v0 - __bfloat162float(h0)),
                __float2bfloat16(v1 - __bfloat162float(h1)));
        }
        {
            const size_t off = ((size_t)b * SEQ + s0 + 8) * HID + d;
            const float v0 = O[nt][2] * inv1, v1 = O[nt][3] * inv1;
            const __nv_bfloat16 h0 = __float2bfloat16(v0);
            const __nv_bfloat16 h1 = __float2bfloat16(v1);
            *reinterpret_cast<__nv_bfloat162*>(g_ah + off) = __halves2bfloat162(h0, h1);
            *reinterpret_cast<__nv_bfloat162*>(g_al + off) = __halves2bfloat162(
                __float2bfloat16(v0 - __bfloat162float(h0)),
                __float2bfloat16(v1 - __bfloat162float(h1)));
        }
    }
}

// ---------------------------------------------------------------------------
// kernel_launch
// ---------------------------------------------------------------------------
extern "C" void kernel_launch(void* const* d_in, const int* in_sizes, int n_in,
                              void* d_out, int out_size)
{
    (void)in_sizes; (void)n_in; (void)out_size;
    const float* hidden = (const float*)d_in[0];
    const float* mask   = (const float*)d_in[1];
    const float* gamma  = (const float*)d_in[2];
    const float* beta   = (const float*)d_in[3];
    const float* Wqkv   = (const float*)d_in[4];
    const float* bqkv   = (const float*)d_in[5];
    const float* Wout   = (const float*)d_in[6];
    const float* bout   = (const float*)d_in[7];
    float* out = (float*)d_out;

    cudaFuncSetAttribute(mm_kernel,
                         cudaFuncAttributeMaxDynamicSharedMemorySize, MM_SMEM);
    cudaFuncSetAttribute(attn_kernel,
                         cudaFuncAttributeMaxDynamicSharedMemorySize, AT_SMEM);

    ln_kernel<<<NTOK, 256>>>(hidden, gamma, beta);
    conv_w<<<dim3(3 * HID / 32, HID / 32), dim3(32, 8)>>>(Wqkv, 0, 3 * HID);
    conv_w<<<dim3(HID / 32, HID / 32), dim3(32, 8)>>>(Wout, 1, HID);
    mm_kernel<<<dim3(3 * HID / 128, NTOK / 128), 256, MM_SMEM>>>(0, bqkv, nullptr, nullptr);
    attn_kernel<<<dim3(SEQ / 128, BATCH * NHEAD), 256, AT_SMEM>>>(mask);
    mm_kernel<<<dim3(HID / 128, NTOK / 128), 256, MM_SMEM>>>(1, bout, hidden, out);
}

// round 14
// speedup vs baseline: 3.9909x; 1.0146x over previous
#include <cuda_runtime.h>
#include <cuda_bf16.h>
#include <cstdint>

// Problem constants
#define HID   1024
#define BATCH 4
#define SEQ   2048
#define NHEAD 16
#define DH    64
#define NTOK  (BATCH * SEQ)   // 8192

// ---------------------------------------------------------------------------
// Scratch (static __device__ arrays; no allocation anywhere)
// ---------------------------------------------------------------------------
// bf16-split activations (LN output, later attention output) [tok][1024]
__device__ __nv_bfloat16 g_ah[(size_t)NTOK * HID];
__device__ __nv_bfloat16 g_al[(size_t)NTOK * HID];
// bf16-split transposed weights [N][K]
__device__ __nv_bfloat16 g_wqh[(size_t)3 * HID * HID];
__device__ __nv_bfloat16 g_wql[(size_t)3 * HID * HID];
__device__ __nv_bfloat16 g_woh[(size_t)HID * HID];
__device__ __nv_bfloat16 g_wol[(size_t)HID * HID];
// attention operands [b*16+h][s][64]
__device__ __nv_bfloat16 g_qh[(size_t)NTOK * HID];
__device__ __nv_bfloat16 g_ql[(size_t)NTOK * HID];
__device__ __nv_bfloat16 g_kh[(size_t)NTOK * HID];
__device__ __nv_bfloat16 g_kl[(size_t)NTOK * HID];
__device__ __nv_bfloat16 g_vh[(size_t)NTOK * HID];

// ---------------------------------------------------------------------------
// Warp-MMA helpers (family-compatible: ldmatrix + mma.sync + cp.async)
// ---------------------------------------------------------------------------
__device__ __forceinline__ uint32_t smem_u32(const void* p) {
    return (uint32_t)__cvta_generic_to_shared(p);
}

__device__ __forceinline__ void cp16(uint32_t dst, const void* src) {
    asm volatile("cp.async.cg.shared.global [%0], [%1], 16;" :: "r"(dst), "l"(src));
}
#define CP_COMMIT() asm volatile("cp.async.commit_group;" ::: "memory")
#define CP_WAIT0()  asm volatile("cp.async.wait_group 0;" ::: "memory")
#define CP_WAIT1()  asm volatile("cp.async.wait_group 1;" ::: "memory")

__device__ __forceinline__ void ldsm_x4(uint32_t* r, uint32_t addr) {
    asm volatile("ldmatrix.sync.aligned.m8n8.x4.shared.b16 {%0,%1,%2,%3}, [%4];"
        : "=r"(r[0]), "=r"(r[1]), "=r"(r[2]), "=r"(r[3]) : "r"(addr));
}
__device__ __forceinline__ void ldsm_x4_t(uint32_t* r, uint32_t addr) {
    asm volatile("ldmatrix.sync.aligned.m8n8.x4.trans.shared.b16 {%0,%1,%2,%3}, [%4];"
        : "=r"(r[0]), "=r"(r[1]), "=r"(r[2]), "=r"(r[3]) : "r"(addr));
}

__device__ __forceinline__ void mma_bf16(float* c, const uint32_t* a, const uint32_t* b) {
    asm volatile(
        "mma.sync.aligned.m16n8k16.row.col.f32.bf16.bf16.f32 "
        "{%0,%1,%2,%3}, {%4,%5,%6,%7}, {%8,%9}, {%0,%1,%2,%3};"
        : "+f"(c[0]), "+f"(c[1]), "+f"(c[2]), "+f"(c[3])
        : "r"(a[0]), "r"(a[1]), "r"(a[2]), "r"(a[3]), "r"(b[0]), "r"(b[1]));
}

__device__ __forceinline__ uint32_t pack_bf16(float lo, float hi) {
    __nv_bfloat162 t = __float22bfloat162_rn(make_float2(lo, hi));
    return *reinterpret_cast<uint32_t*>(&t);
}

// ---------------------------------------------------------------------------
// 1) LayerNorm fused with bf16 hi/lo split -> g_ah / g_al
// ---------------------------------------------------------------------------
__global__ __launch_bounds__(256) void ln_kernel(
    const float* __restrict__ x,
    const float* __restrict__ gamma,
    const float* __restrict__ beta)
{
    const int t   = blockIdx.x;
    const int tid = threadIdx.x;

    const float4 f = reinterpret_cast<const float4*>(x + (size_t)t * HID)[tid];
    float s  = f.x + f.y + f.z + f.w;
    float ss = f.x * f.x + f.y * f.y + f.z * f.z + f.w * f.w;

    #pragma unroll
    for (int m = 16; m; m >>= 1) {
        s  += __shfl_xor_sync(0xffffffffu, s,  m);
        ss += __shfl_xor_sync(0xffffffffu, ss, m);
    }
    __shared__ float red0[8], red1[8];
    const int w = tid >> 5, l = tid & 31;
    if (l == 0) { red0[w] = s; red1[w] = ss; }
    __syncthreads();
    s = 0.f; ss = 0.f;
    #pragma unroll
    for (int i = 0; i < 8; i++) { s += red0[i]; ss += red1[i]; }

    const float mean = s * (1.0f / HID);
    const float var  = ss * (1.0f / HID) - mean * mean;
    const float rstd = rsqrtf(var + 1e-12f);

    const float4 g = reinterpret_cast<const float4*>(gamma)[tid];
    const float4 b = reinterpret_cast<const float4*>(beta)[tid];
    float o[4];
    o[0] = (f.x - mean) * rstd * g.x + b.x;
    o[1] = (f.y - mean) * rstd * g.y + b.y;
    o[2] = (f.z - mean) * rstd * g.z + b.z;
    o[3] = (f.w - mean) * rstd * g.w + b.w;

    const size_t off = (size_t)t * HID + tid * 4;
    __nv_bfloat16 h[4], lo[4];
    #pragma unroll
    for (int i = 0; i < 4; i++) {
        h[i]  = __float2bfloat16(o[i]);
        lo[i] = __float2bfloat16(o[i] - __bfloat162float(h[i]));
    }
    *reinterpret_cast<__nv_bfloat162*>(g_ah + off)     = __halves2bfloat162(h[0], h[1]);
    *reinterpret_cast<__nv_bfloat162*>(g_ah + off + 2) = __halves2bfloat162(h[2], h[3]);
    *reinterpret_cast<__nv_bfloat162*>(g_al + off)     = __halves2bfloat162(lo[0], lo[1]);
    *reinterpret_cast<__nv_bfloat162*>(g_al + off + 2) = __halves2bfloat162(lo[2], lo[3]);
}

// ---------------------------------------------------------------------------
// 2) Transpose + split weights: W [K=1024][Ndim] -> T{h,l} [Ndim][1024]
// ---------------------------------------------------------------------------
__global__ __launch_bounds__(256) void conv_w(const float* __restrict__ W,
                                              int which, int Ndim)
{
    __nv_bfloat16* Th = which ? g_woh : g_wqh;
    __nv_bfloat16* Tl = which ? g_wol : g_wql;

    __shared__ float t[32][33];
    const int n0 = blockIdx.x * 32, k0 = blockIdx.y * 32;
    const int x = threadIdx.x, y = threadIdx.y;

    #pragma unroll
    for (int i = 0; i < 4; i++)
        t[y + i * 8][x] = W[(size_t)(k0 + y + i * 8) * Ndim + n0 + x];
    __syncthreads();

    #pragma unroll
    for (int i = 0; i < 4; i++) {
        const int n = n0 + y + i * 8;
        const int k = k0 + x;
        const float v = t[x][y + i * 8];
        const __nv_bfloat16 h = __float2bfloat16(v);
        Th[(size_t)n * HID + k] = h;
        Tl[(size_t)n * HID + k] = __float2bfloat16(v - __bfloat162float(h));
    }
}

// ---------------------------------------------------------------------------
// 3) Tensor-core GEMM (mma.sync bf16), CTA 128x128, BK=32, 3-stage pipeline.
//    WHICH=0: QKV, 3-term hi/lo split, epilogue emits q-split/k-split/v.
//    WHICH=1: OUT, single-term (Ah*Bh), epilogue bias+resid -> outp.
// ---------------------------------------------------------------------------
#define MM0_SMEM (3 * 32768)
#define MM1_SMEM (3 * 16384)

template<int WHICH>
__global__ __launch_bounds__(256) void mm_kernel(
    const float* __restrict__ bias,
    const float* __restrict__ resid, float* __restrict__ outp)
{
    constexpr bool SPLIT = (WHICH == 0);
    constexpr uint32_t BUFB = SPLIT ? 32768u : 16384u;

    extern __shared__ char smem[];
    const uint32_t sb = smem_u32(smem);
    const int tid  = threadIdx.x;
    const int lane = tid & 31;
    const int wid  = tid >> 5;
    const int wm   = wid >> 2;
    const int wn   = wid & 3;
    const int row0 = blockIdx.y * 128;
    const int col0 = blockIdx.x * 128;

    const __nv_bfloat16* Ah = g_ah + (size_t)row0 * HID;
    const __nv_bfloat16* Al = g_al + (size_t)row0 * HID;
    const __nv_bfloat16* Bh = (WHICH ? g_woh : g_wqh) + (size_t)col0 * HID;
    const __nv_bfloat16* Bl = (WHICH ? g_wol : g_wql) + (size_t)col0 * HID;

    float C[4][4][4];
    #pragma unroll
    for (int i = 0; i < 4; i++)
        #pragma unroll
        for (int j = 0; j < 4; j++)
            #pragma unroll
            for (int k = 0; k < 4; k++) C[i][j][k] = 0.f;

    auto load_slab = [&](int kt, int buf) {
        const uint32_t base = sb + (uint32_t)buf * BUFB;
        constexpr int ITERS = SPLIT ? 8 : 4;
        #pragma unroll
        for (int it = 0; it < ITERS; it++) {
            const int c   = it * 256 + tid;
            const int arr = c >> 9;          // SPLIT: 0AH 1AL 2BH 3BL; else 0AH 1BH
            const int cc  = c & 511;
            const int r   = cc >> 2;
            const int j   = cc & 3;
            const uint32_t soff = (uint32_t)(arr * 8192 + r * 64 +
                                             ((j ^ ((r >> 1) & 3)) << 4));
            const __nv_bfloat16* src;
            if (SPLIT)
                src = (arr == 0 ? Ah : arr == 1 ? Al : arr == 2 ? Bh : Bl);
            else
                src = (arr == 0 ? Ah : Bh);
            cp16(base + soff, src + (size_t)r * HID + kt * 32 + j * 8);
        }
    };

    auto compute = [&](int buf) {
        const uint32_t base = sb + (uint32_t)buf * BUFB;
        const uint32_t bboff = SPLIT ? 16384u : 8192u;
        #pragma unroll
        for (int ks = 0; ks < 2; ks++) {
            uint32_t ah[4][4], al[4][4], bh[4][2], bl[4][2];
            #pragma unroll
            for (int mt = 0; mt < 4; mt++) {
                const int r  = wm * 64 + mt * 16 + (lane & 15);
                const int jc = ks * 2 + (lane >> 4);
                const uint32_t addr = base + (uint32_t)(r * 64 +
                                        ((jc ^ ((r >> 1) & 3)) << 4));
                ldsm_x4(ah[mt], addr);
                if (SPLIT) ldsm_x4(al[mt], addr + 8192);
            }
            #pragma unroll
            for (int p = 0; p < 2; p++) {
                const int r  = wn * 32 + p * 16 + (lane & 7) + ((lane >> 4) << 3);
                const int jc = ks * 2 + ((lane >> 3) & 1);
                const uint32_t addr = base + bboff + (uint32_t)(r * 64 +
                                        ((jc ^ ((r >> 1) & 3)) << 4));
                uint32_t t4[4];
                ldsm_x4(t4, addr);
                bh[2 * p][0] = t4[0]; bh[2 * p][1] = t4[1];
                bh[2 * p + 1][0] = t4[2]; bh[2 * p + 1][1] = t4[3];
                if (SPLIT) {
                    ldsm_x4(t4, addr + 8192);
                    bl[2 * p][0] = t4[0]; bl[2 * p][1] = t4[1];
                    bl[2 * p + 1][0] = t4[2]; bl[2 * p + 1][1] = t4[3];
                }
            }
            #pragma unroll
            for (int mt = 0; mt < 4; mt++)
                #pragma unroll
                for (int nt = 0; nt < 4; nt++) {
                    mma_bf16(C[mt][nt], ah[mt], bh[nt]);
                    if (SPLIT) {
                        mma_bf16(C[mt][nt], ah[mt], bl[nt]);
                        mma_bf16(C[mt][nt], al[mt], bh[nt]);
                    }
                }
        }
    };

    // ---- 3-stage pipelined K loop (32 slabs), one barrier per slab ----
    load_slab(0, 0);
    CP_COMMIT();
    load_slab(1, 1);
    CP_COMMIT();
    int cur = 0;
    for (int kt = 0; kt < 32; kt++) {
        if (kt + 2 < 32) { CP_WAIT1(); } else { CP_WAIT0(); }
        __syncthreads();
        if (kt + 2 < 32) {
            int nb = cur + 2; if (nb >= 3) nb -= 3;
            load_slab(kt + 2, nb);
            CP_COMMIT();
        }
        compute(cur);
        if (++cur == 3) cur = 0;
    }

    // ---- epilogue ----
    const int r_lane = lane >> 2;
    const int c_lane = (lane & 3) * 2;

    #pragma unroll
    for (int mt = 0; mt < 4; mt++) {
        #pragma unroll
        for (int half = 0; half < 2; half++) {
            const int m  = row0 + wm * 64 + mt * 16 + r_lane + half * 8;
            const int b_ = m >> 11;
            const int s_ = m & 2047;
            #pragma unroll
            for (int nt = 0; nt < 4; nt++) {
                const int n = col0 + wn * 32 + nt * 8 + c_lane;
                float v0 = C[mt][nt][half * 2 + 0] + bias[n];
                float v1 = C[mt][nt][half * 2 + 1] + bias[n + 1];
                if (WHICH) {
                    const size_t off = (size_t)m * HID + n;
                    const float2 rr = *reinterpret_cast<const float2*>(resid + off);
                    *reinterpret_cast<float2*>(outp + off) =
                        make_float2(v0 + rr.x, v1 + rr.y);
                } else {
                    const int part = n >> 10;
                    const int h = (n & 1023) >> 6;
                    const int d = n & 63;
                    const size_t off =
                        (((size_t)(b_ * NHEAD + h)) * SEQ + s_) * DH + d;
                    if (part == 0) {
                        v0 *= 0.125f; v1 *= 0.125f;   // fold 1/sqrt(DH)
                        __nv_bfloat16 h0 = __float2bfloat16(v0);
                        __nv_bfloat16 h1 = __float2bfloat16(v1);
                        *reinterpret_cast<__nv_bfloat162*>(g_qh + off) =
                            __halves2bfloat162(h0, h1);
                        *reinterpret_cast<__nv_bfloat162*>(g_ql + off) =
                            __halves2bfloat162(
                                __float2bfloat16(v0 - __bfloat162float(h0)),
                                __float2bfloat16(v1 - __bfloat162float(h1)));
                    } else if (part == 1) {
                        __nv_bfloat16 h0 = __float2bfloat16(v0);
                        __nv_bfloat16 h1 = __float2bfloat16(v1);
                        *reinterpret_cast<__nv_bfloat162*>(g_kh + off) =
                            __halves2bfloat162(h0, h1);
                        *reinterpret_cast<__nv_bfloat162*>(g_kl + off) =
                            __halves2bfloat162(
                                __float2bfloat16(v0 - __bfloat162float(h0)),
                                __float2bfloat16(v1 - __bfloat162float(h1)));
                    } else {
                        *reinterpret_cast<__nv_bfloat162*>(g_vh + off) =
                            __halves2bfloat162(__float2bfloat16(v0),
                                               __float2bfloat16(v1));
                    }
                }
            }
        }
    }
}

// ---------------------------------------------------------------------------
// 4) Tensor-core flash attention, 3-stage KV pipeline, one barrier per tile.
//    Grid (16 q-tiles, 64 bh), 256 threads = 8 warps, warp owns 16 q-rows.
//    Output -> g_ah only (OUT GEMM is single-term).
// ---------------------------------------------------------------------------
#define AQ_L   16384
#define ABUF   32768
#define ABUFS  25856
#define AK_L   8192
#define AV     16384
#define AMSK   25600
#define AT_SMEM (ABUF + 3 * ABUFS)   // 110336

__global__ __launch_bounds__(256) void attn_kernel(const float* __restrict__ mask)
{
    extern __shared__ char smem[];
    const uint32_t sb = smem_u32(smem);
    const int tid  = threadIdx.x;
    const int lane = tid & 31;
    const int wid  = tid >> 5;
    const int bh   = blockIdx.y;
    const int b    = bh >> 4;
    const int h    = bh & 15;
    const int qt   = blockIdx.x;

    const __nv_bfloat16* Qh = g_qh + ((size_t)bh * SEQ + (size_t)qt * 128) * DH;
    const __nv_bfloat16* Ql = g_ql + ((size_t)bh * SEQ + (size_t)qt * 128) * DH;
    const __nv_bfloat16* Kh = g_kh + (size_t)bh * SEQ * DH;
    const __nv_bfloat16* Kl = g_kl + (size_t)bh * SEQ * DH;
    const __nv_bfloat16* Vv = g_vh + (size_t)bh * SEQ * DH;
    const float* mk = mask + (size_t)b * SEQ;

    // ---- load Q tile (128 rows x 64, hi+lo): 2048 16B chunks ----
    #pragma unroll
    for (int it = 0; it < 8; it++) {
        const int c   = it * 256 + tid;
        const int arr = c >> 10;
        const int cc  = c & 1023;
        const int r   = cc >> 3, j = cc & 7;
        const uint32_t soff = (uint32_t)((arr ? AQ_L : 0) + r * 128 +
                                         ((j ^ (r & 7)) << 4));
        cp16(sb + soff, (arr ? Ql : Qh) + (size_t)r * DH + j * 8);
    }

    auto load_kv = [&](int kt, int buf) {
        const uint32_t base = sb + ABUF + (uint32_t)buf * ABUFS;
        #pragma unroll
        for (int it = 0; it < 7; it++) {
            const int c = it * 256 + tid;
            if (c < 1536) {
                const int arr = c >> 9;     // 0 KH, 1 KL, 2 V
                const int cc  = c & 511;
                const int r   = cc >> 3, j = cc & 7;
                if (arr < 2) {
                    const uint32_t soff = (uint32_t)((arr ? AK_L : 0) + r * 128 +
                                                     ((j ^ (r & 7)) << 4));
                    cp16(base + soff,
                         (arr ? Kl : Kh) + ((size_t)kt * 64 + r) * DH + j * 8);
                } else {
                    cp16(base + AV + (uint32_t)(r * 144 + j * 16),
                         Vv + ((size_t)kt * 64 + r) * DH + j * 8);
                }
            } else if (c < 1552) {
                const int j = c - 1536;
                cp16(base + AMSK + (uint32_t)(j * 16), mk + kt * 64 + j * 4);
            }
        }
    };

    float O[8][4];
    #pragma unroll
    for (int i = 0; i < 8; i++)
        #pragma unroll
        for (int j = 0; j < 4; j++) O[i][j] = 0.f;
    float m_run[2] = {-1e30f, -1e30f};
    float l_run[2] = {0.f, 0.f};

    load_kv(0, 0);
    CP_COMMIT();
    load_kv(1, 1);
    CP_COMMIT();

    int cur = 0;
    for (int kt = 0; kt < SEQ / 64; kt++) {
        if (kt + 2 < SEQ / 64) { CP_WAIT1(); } else { CP_WAIT0(); }
        __syncthreads();
        if (kt + 2 < SEQ / 64) {
            int nb = cur + 2; if (nb >= 3) nb -= 3;
            load_kv(kt + 2, nb);
            CP_COMMIT();
        }

        const uint32_t kbase = sb + ABUF + (uint32_t)cur * ABUFS;

        // ---- S = Q' @ K^T  (3-term split) ----
        float C[8][4];
        #pragma unroll
        for (int i = 0; i < 8; i++)
            #pragma unroll
            for (int j = 0; j < 4; j++) C[i][j] = 0.f;

        #pragma unroll
        for (int kd = 0; kd < 4; kd++) {
            uint32_t ah[4], al[4];
            {
                const int r  = wid * 16 + (lane & 15);
                const int jc = kd * 2 + (lane >> 4);
                const uint32_t addr = sb + (uint32_t)(r * 128 +
                                        ((jc ^ (r & 7)) << 4));
                ldsm_x4(ah, addr);
                ldsm_x4(al, addr + AQ_L);
            }
            #pragma unroll
            for (int p = 0; p < 4; p++) {
                const int r  = p * 16 + (lane & 7) + ((lane >> 4) << 3);
                const int jc = kd * 2 + ((lane >> 3) & 1);
                const uint32_t addr = kbase + (uint32_t)(r * 128 +
                                        ((jc ^ (r & 7)) << 4));
                uint32_t th[4], tl[4];
                ldsm_x4(th, addr);
                ldsm_x4(tl, addr + AK_L);
                mma_bf16(C[2 * p],     ah, th);
                mma_bf16(C[2 * p],     ah, tl);
                mma_bf16(C[2 * p],     al, th);
                mma_bf16(C[2 * p + 1], ah, th + 2);
                mma_bf16(C[2 * p + 1], ah, tl + 2);
                mma_bf16(C[2 * p + 1], al, th + 2);
            }
        }

        // ---- online softmax (rows g = lane>>2 and g+8) ----
        const float* msk = reinterpret_cast<const float*>(
            smem + ABUF + (size_t)cur * ABUFS + AMSK);
        const int c0 = (lane & 3) * 2;

        float mloc0 = -1e30f, mloc1 = -1e30f;
        #pragma unroll
        for (int nt = 0; nt < 8; nt++) {
            const float mv0 = msk[nt * 8 + c0];
            const float mv1 = msk[nt * 8 + c0 + 1];
            C[nt][0] += mv0; C[nt][1] += mv1;
            C[nt][2] += mv0; C[nt][3] += mv1;
            mloc0 = fmaxf(mloc0, fmaxf(C[nt][0], C[nt][1]));
            mloc1 = fmaxf(mloc1, fmaxf(C[nt][2], C[nt][3]));
        }
        mloc0 = fmaxf(mloc0, __shfl_xor_sync(0xffffffffu, mloc0, 1));
        mloc0 = fmaxf(mloc0, __shfl_xor_sync(0xffffffffu, mloc0, 2));
        mloc1 = fmaxf(mloc1, __shfl_xor_sync(0xffffffffu, mloc1, 1));
        mloc1 = fmaxf(mloc1, __shfl_xor_sync(0xffffffffu, mloc1, 2));

        const float mnew0 = fmaxf(m_run[0], mloc0);
        const float mnew1 = fmaxf(m_run[1], mloc1);
        const float corr0 = __expf(m_run[0] - mnew0);
        const float corr1 = __expf(m_run[1] - mnew1);

        float ls0 = 0.f, ls1 = 0.f;
        #pragma unroll
        for (int nt = 0; nt < 8; nt++) {
            C[nt][0] = __expf(C[nt][0] - mnew0);
            C[nt][1] = __expf(C[nt][1] - mnew0);
            C[nt][2] = __expf(C[nt][2] - mnew1);
            C[nt][3] = __expf(C[nt][3] - mnew1);
            ls0 += C[nt][0] + C[nt][1];
            ls1 += C[nt][2] + C[nt][3];
        }
        ls0 += __shfl_xor_sync(0xffffffffu, ls0, 1);
        ls0 += __shfl_xor_sync(0xffffffffu, ls0, 2);
        ls1 += __shfl_xor_sync(0xffffffffu, ls1, 1);
        ls1 += __shfl_xor_sync(0xffffffffu, ls1, 2);

        l_run[0] = l_run[0] * corr0 + ls0;
        l_run[1] = l_run[1] * corr1 + ls1;
        m_run[0] = mnew0;
        m_run[1] = mnew1;

        #pragma unroll
        for (int nt = 0; nt < 8; nt++) {
            O[nt][0] *= corr0; O[nt][1] *= corr0;
            O[nt][2] *= corr1; O[nt][3] *= corr1;
        }

        // ---- pack P (C-frag -> A-frag identity) ----
        uint32_t pa[4][4];
        #pragma unroll
        for (int kc = 0; kc < 4; kc++) {
            pa[kc][0] = pack_bf16(C[2 * kc][0],     C[2 * kc][1]);
            pa[kc][1] = pack_bf16(C[2 * kc][2],     C[2 * kc][3]);
            pa[kc][2] = pack_bf16(C[2 * kc + 1][0], C[2 * kc + 1][1]);
            pa[kc][3] = pack_bf16(C[2 * kc + 1][2], C[2 * kc + 1][3]);
        }

        // ---- O += P @ V ----
        #pragma unroll
        for (int kc = 0; kc < 4; kc++) {
            #pragma unroll
            for (int np = 0; np < 4; np++) {
                const int r = kc * 16 + (lane & 7) + (((lane >> 3) & 1) << 3);
                const int jc = 2 * np + (lane >> 4);
                const uint32_t addr = kbase + AV + (uint32_t)(r * 144 + jc * 16);
                uint32_t t4[4];
                ldsm_x4_t(t4, addr);
                mma_bf16(O[2 * np],     pa[kc], t4);
                mma_bf16(O[2 * np + 1], pa[kc], t4 + 2);
            }
        }

        if (++cur == 3) cur = 0;
    }

    // ---- epilogue: normalize, write bf16 hi into g_ah [b][s][h*64+d] ----
    const float inv0 = 1.0f / l_run[0];
    const float inv1 = 1.0f / l_run[1];
    const int g  = lane >> 2;
    const int s0 = qt * 128 + wid * 16 + g;
    const int c0 = (lane & 3) * 2;

    #pragma unroll
    for (int nt = 0; nt < 8; nt++) {
        const int d = h * DH + nt * 8 + c0;
        {
            const size_t off = ((size_t)b * SEQ + s0) * HID + d;
            *reinterpret_cast<__nv_bfloat162*>(g_ah + off) =
                __halves2bfloat162(__float2bfloat16(O[nt][0] * inv0),
                                   __float2bfloat16(O[nt][1] * inv0));
        }
        {
            const size_t off = ((size_t)b * SEQ + s0 + 8) * HID + d;
            *reinterpret_cast<__nv_bfloat162*>(g_ah + off) =
                __halves2bfloat162(__float2bfloat16(O[nt][2] * inv1),
                                   __float2bfloat16(O[nt][3] * inv1));
        }
    }
}

// ---------------------------------------------------------------------------
// kernel_launch
// ---------------------------------------------------------------------------
extern "C" void kernel_launch(void* const* d_in, const int* in_sizes, int n_in,
                              void* d_out, int out_size)
{
    (void)in_sizes; (void)n_in; (void)out_size;
    const float* hidden = (const float*)d_in[0];
    const float* mask   = (const float*)d_in[1];
    const float* gamma  = (const float*)d_in[2];
    const float* beta   = (const float*)d_in[3];
    const float* Wqkv   = (const float*)d_in[4];
    const float* bqkv   = (const float*)d_in[5];
    const float* Wout   = (const float*)d_in[6];
    const float* bout   = (const float*)d_in[7];
    float* out = (float*)d_out;

    cudaFuncSetAttribute(mm_kernel<0>,
                         cudaFuncAttributeMaxDynamicSharedMemorySize, MM0_SMEM);
    cudaFuncSetAttribute(mm_kernel<1>,
                         cudaFuncAttributeMaxDynamicSharedMemorySize, MM1_SMEM);
    cudaFuncSetAttribute(attn_kernel,
                         cudaFuncAttributeMaxDynamicSharedMemorySize, AT_SMEM);

    ln_kernel<<<NTOK, 256>>>(hidden, gamma, beta);
    conv_w<<<dim3(3 * HID / 32, HID / 32), dim3(32, 8)>>>(Wqkv, 0, 3 * HID);
    conv_w<<<dim3(HID / 32, HID / 32), dim3(32, 8)>>>(Wout, 1, HID);
    mm_kernel<0><<<dim3(3 * HID / 128, NTOK / 128), 256, MM0_SMEM>>>(bqkv, nullptr, nullptr);
    attn_kernel<<<dim3(SEQ / 128, BATCH * NHEAD), 256, AT_SMEM>>>(mask);
    mm_kernel<1><<<dim3(HID / 128, NTOK / 128), 256, MM1_SMEM>>>(bout, hidden, out);
}

// round 15
// speedup vs baseline: 4.0000x; 1.0023x over previous
#include <cuda_runtime.h>
#include <cuda_bf16.h>
#include <cstdint>

// Problem constants
#define HID   1024
#define BATCH 4
#define SEQ   2048
#define NHEAD 16
#define DH    64
#define NTOK  (BATCH * SEQ)   // 8192

// ---------------------------------------------------------------------------
// Scratch (static __device__ arrays; no allocation anywhere)
// ---------------------------------------------------------------------------
// bf16-split activations (LN output, later attention output) [tok][1024]
__device__ __nv_bfloat16 g_ah[(size_t)NTOK * HID];
__device__ __nv_bfloat16 g_al[(size_t)NTOK * HID];
// bf16-split transposed weights [N][K]
__device__ __nv_bfloat16 g_wqh[(size_t)3 * HID * HID];
__device__ __nv_bfloat16 g_wql[(size_t)3 * HID * HID];
__device__ __nv_bfloat16 g_woh[(size_t)HID * HID];
__device__ __nv_bfloat16 g_wol[(size_t)HID * HID];
// attention operands [b*16+h][s][64]
__device__ __nv_bfloat16 g_qh[(size_t)NTOK * HID];
__device__ __nv_bfloat16 g_ql[(size_t)NTOK * HID];
__device__ __nv_bfloat16 g_kh[(size_t)NTOK * HID];
__device__ __nv_bfloat16 g_kl[(size_t)NTOK * HID];
__device__ __nv_bfloat16 g_vh[(size_t)NTOK * HID];

// ---------------------------------------------------------------------------
// Warp-MMA helpers (family-compatible: ldmatrix + mma.sync + cp.async)
// ---------------------------------------------------------------------------
__device__ __forceinline__ uint32_t smem_u32(const void* p) {
    return (uint32_t)__cvta_generic_to_shared(p);
}

__device__ __forceinline__ void cp16(uint32_t dst, const void* src) {
    asm volatile("cp.async.cg.shared.global [%0], [%1], 16;" :: "r"(dst), "l"(src));
}
#define CP_COMMIT() asm volatile("cp.async.commit_group;" ::: "memory")
#define CP_WAIT0()  asm volatile("cp.async.wait_group 0;" ::: "memory")
#define CP_WAIT1()  asm volatile("cp.async.wait_group 1;" ::: "memory")

__device__ __forceinline__ void ldsm_x4(uint32_t* r, uint32_t addr) {
    asm volatile("ldmatrix.sync.aligned.m8n8.x4.shared.b16 {%0,%1,%2,%3}, [%4];"
        : "=r"(r[0]), "=r"(r[1]), "=r"(r[2]), "=r"(r[3]) : "r"(addr));
}
__device__ __forceinline__ void ldsm_x4_t(uint32_t* r, uint32_t addr) {
    asm volatile("ldmatrix.sync.aligned.m8n8.x4.trans.shared.b16 {%0,%1,%2,%3}, [%4];"
        : "=r"(r[0]), "=r"(r[1]), "=r"(r[2]), "=r"(r[3]) : "r"(addr));
}

__device__ __forceinline__ void mma_bf16(float* c, const uint32_t* a, const uint32_t* b) {
    asm volatile(
        "mma.sync.aligned.m16n8k16.row.col.f32.bf16.bf16.f32 "
        "{%0,%1,%2,%3}, {%4,%5,%6,%7}, {%8,%9}, {%0,%1,%2,%3};"
        : "+f"(c[0]), "+f"(c[1]), "+f"(c[2]), "+f"(c[3])
        : "r"(a[0]), "r"(a[1]), "r"(a[2]), "r"(a[3]), "r"(b[0]), "r"(b[1]));
}

__device__ __forceinline__ uint32_t pack_bf16(float lo, float hi) {
    __nv_bfloat162 t = __float22bfloat162_rn(make_float2(lo, hi));
    return *reinterpret_cast<uint32_t*>(&t);
}

// ---------------------------------------------------------------------------
// 1) LayerNorm fused with bf16 hi/lo split -> g_ah / g_al
// ---------------------------------------------------------------------------
__global__ __launch_bounds__(256) void ln_kernel(
    const float* __restrict__ x,
    const float* __restrict__ gamma,
    const float* __restrict__ beta)
{
    const int t   = blockIdx.x;
    const int tid = threadIdx.x;

    const float4 f = reinterpret_cast<const float4*>(x + (size_t)t * HID)[tid];
    float s  = f.x + f.y + f.z + f.w;
    float ss = f.x * f.x + f.y * f.y + f.z * f.z + f.w * f.w;

    #pragma unroll
    for (int m = 16; m; m >>= 1) {
        s  += __shfl_xor_sync(0xffffffffu, s,  m);
        ss += __shfl_xor_sync(0xffffffffu, ss, m);
    }
    __shared__ float red0[8], red1[8];
    const int w = tid >> 5, l = tid & 31;
    if (l == 0) { red0[w] = s; red1[w] = ss; }
    __syncthreads();
    s = 0.f; ss = 0.f;
    #pragma unroll
    for (int i = 0; i < 8; i++) { s += red0[i]; ss += red1[i]; }

    const float mean = s * (1.0f / HID);
    const float var  = ss * (1.0f / HID) - mean * mean;
    const float rstd = rsqrtf(var + 1e-12f);

    const float4 g = reinterpret_cast<const float4*>(gamma)[tid];
    const float4 b = reinterpret_cast<const float4*>(beta)[tid];
    float o[4];
    o[0] = (f.x - mean) * rstd * g.x + b.x;
    o[1] = (f.y - mean) * rstd * g.y + b.y;
    o[2] = (f.z - mean) * rstd * g.z + b.z;
    o[3] = (f.w - mean) * rstd * g.w + b.w;

    const size_t off = (size_t)t * HID + tid * 4;
    __nv_bfloat16 h[4], lo[4];
    #pragma unroll
    for (int i = 0; i < 4; i++) {
        h[i]  = __float2bfloat16(o[i]);
        lo[i] = __float2bfloat16(o[i] - __bfloat162float(h[i]));
    }
    *reinterpret_cast<__nv_bfloat162*>(g_ah + off)     = __halves2bfloat162(h[0], h[1]);
    *reinterpret_cast<__nv_bfloat162*>(g_ah + off + 2) = __halves2bfloat162(h[2], h[3]);
    *reinterpret_cast<__nv_bfloat162*>(g_al + off)     = __halves2bfloat162(lo[0], lo[1]);
    *reinterpret_cast<__nv_bfloat162*>(g_al + off + 2) = __halves2bfloat162(lo[2], lo[3]);
}

// ---------------------------------------------------------------------------
// 2) Transpose + split weights: W [K=1024][Ndim] -> T{h,l} [Ndim][1024]
// ---------------------------------------------------------------------------
__global__ __launch_bounds__(256) void conv_w(const float* __restrict__ W,
                                              int which, int Ndim)
{
    __nv_bfloat16* Th = which ? g_woh : g_wqh;
    __nv_bfloat16* Tl = which ? g_wol : g_wql;

    __shared__ float t[32][33];
    const int n0 = blockIdx.x * 32, k0 = blockIdx.y * 32;
    const int x = threadIdx.x, y = threadIdx.y;

    #pragma unroll
    for (int i = 0; i < 4; i++)
        t[y + i * 8][x] = W[(size_t)(k0 + y + i * 8) * Ndim + n0 + x];
    __syncthreads();

    #pragma unroll
    for (int i = 0; i < 4; i++) {
        const int n = n0 + y + i * 8;
        const int k = k0 + x;
        const float v = t[x][y + i * 8];
        const __nv_bfloat16 h = __float2bfloat16(v);
        Th[(size_t)n * HID + k] = h;
        Tl[(size_t)n * HID + k] = __float2bfloat16(v - __bfloat162float(h));
    }
}

// ---------------------------------------------------------------------------
// 3) Tensor-core GEMM (mma.sync bf16), CTA 128x128, BK=32, 3-stage pipeline.
//    WHICH=0: QKV, 3-term hi/lo split, epilogue emits q-split/k-split/v.
//    WHICH=1: OUT, single-term (Ah*Bh), epilogue bias+resid -> outp.
// ---------------------------------------------------------------------------
#define MM0_SMEM (3 * 32768)
#define MM1_SMEM (3 * 16384)

template<int WHICH>
__global__ __launch_bounds__(256) void mm_kernel(
    const float* __restrict__ bias,
    const float* __restrict__ resid, float* __restrict__ outp)
{
    constexpr bool SPLIT = (WHICH == 0);
    constexpr uint32_t BUFB = SPLIT ? 32768u : 16384u;

    extern __shared__ char smem[];
    const uint32_t sb = smem_u32(smem);
    const int tid  = threadIdx.x;
    const int lane = tid & 31;
    const int wid  = tid >> 5;
    const int wm   = wid >> 2;
    const int wn   = wid & 3;
    const int row0 = blockIdx.y * 128;
    const int col0 = blockIdx.x * 128;

    const __nv_bfloat16* Ah = g_ah + (size_t)row0 * HID;
    const __nv_bfloat16* Al = g_al + (size_t)row0 * HID;
    const __nv_bfloat16* Bh = (WHICH ? g_woh : g_wqh) + (size_t)col0 * HID;
    const __nv_bfloat16* Bl = (WHICH ? g_wol : g_wql) + (size_t)col0 * HID;

    float C[4][4][4];
    #pragma unroll
    for (int i = 0; i < 4; i++)
        #pragma unroll
        for (int j = 0; j < 4; j++)
            #pragma unroll
            for (int k = 0; k < 4; k++) C[i][j][k] = 0.f;

    auto load_slab = [&](int kt, int buf) {
        const uint32_t base = sb + (uint32_t)buf * BUFB;
        constexpr int ITERS = SPLIT ? 8 : 4;
        #pragma unroll
        for (int it = 0; it < ITERS; it++) {
            const int c   = it * 256 + tid;
            const int arr = c >> 9;          // SPLIT: 0AH 1AL 2BH 3BL; else 0AH 1BH
            const int cc  = c & 511;
            const int r   = cc >> 2;
            const int j   = cc & 3;
            const uint32_t soff = (uint32_t)(arr * 8192 + r * 64 +
                                             ((j ^ ((r >> 1) & 3)) << 4));
            const __nv_bfloat16* src;
            if (SPLIT)
                src = (arr == 0 ? Ah : arr == 1 ? Al : arr == 2 ? Bh : Bl);
            else
                src = (arr == 0 ? Ah : Bh);
            cp16(base + soff, src + (size_t)r * HID + kt * 32 + j * 8);
        }
    };

    auto compute = [&](int buf) {
        const uint32_t base = sb + (uint32_t)buf * BUFB;
        const uint32_t bboff = SPLIT ? 16384u : 8192u;
        #pragma unroll
        for (int ks = 0; ks < 2; ks++) {
            uint32_t ah[4][4], al[4][4], bh[4][2], bl[4][2];
            #pragma unroll
            for (int mt = 0; mt < 4; mt++) {
                const int r  = wm * 64 + mt * 16 + (lane & 15);
                const int jc = ks * 2 + (lane >> 4);
                const uint32_t addr = base + (uint32_t)(r * 64 +
                                        ((jc ^ ((r >> 1) & 3)) << 4));
                ldsm_x4(ah[mt], addr);
                if (SPLIT) ldsm_x4(al[mt], addr + 8192);
            }
            #pragma unroll
            for (int p = 0; p < 2; p++) {
                const int r  = wn * 32 + p * 16 + (lane & 7) + ((lane >> 4) << 3);
                const int jc = ks * 2 + ((lane >> 3) & 1);
                const uint32_t addr = base + bboff + (uint32_t)(r * 64 +
                                        ((jc ^ ((r >> 1) & 3)) << 4));
                uint32_t t4[4];
                ldsm_x4(t4, addr);
                bh[2 * p][0] = t4[0]; bh[2 * p][1] = t4[1];
                bh[2 * p + 1][0] = t4[2]; bh[2 * p + 1][1] = t4[3];
                if (SPLIT) {
                    ldsm_x4(t4, addr + 8192);
                    bl[2 * p][0] = t4[0]; bl[2 * p][1] = t4[1];
                    bl[2 * p + 1][0] = t4[2]; bl[2 * p + 1][1] = t4[3];
                }
            }
            #pragma unroll
            for (int mt = 0; mt < 4; mt++)
                #pragma unroll
                for (int nt = 0; nt < 4; nt++) {
                    mma_bf16(C[mt][nt], ah[mt], bh[nt]);
                    if (SPLIT) {
                        mma_bf16(C[mt][nt], ah[mt], bl[nt]);
                        mma_bf16(C[mt][nt], al[mt], bh[nt]);
                    }
                }
        }
    };

    // ---- 3-stage pipelined K loop (32 slabs), one barrier per slab ----
    load_slab(0, 0);
    CP_COMMIT();
    load_slab(1, 1);
    CP_COMMIT();
    int cur = 0;
    for (int kt = 0; kt < 32; kt++) {
        if (kt + 2 < 32) { CP_WAIT1(); } else { CP_WAIT0(); }
        __syncthreads();
        if (kt + 2 < 32) {
            int nb = cur + 2; if (nb >= 3) nb -= 3;
            load_slab(kt + 2, nb);
            CP_COMMIT();
        }
        compute(cur);
        if (++cur == 3) cur = 0;
    }

    // ---- epilogue ----
    const int r_lane = lane >> 2;
    const int c_lane = (lane & 3) * 2;

    #pragma unroll
    for (int mt = 0; mt < 4; mt++) {
        #pragma unroll
        for (int half = 0; half < 2; half++) {
            const int m  = row0 + wm * 64 + mt * 16 + r_lane + half * 8;
            const int b_ = m >> 11;
            const int s_ = m & 2047;
            #pragma unroll
            for (int nt = 0; nt < 4; nt++) {
                const int n = col0 + wn * 32 + nt * 8 + c_lane;
                float v0 = C[mt][nt][half * 2 + 0] + bias[n];
                float v1 = C[mt][nt][half * 2 + 1] + bias[n + 1];
                if (WHICH) {
                    const size_t off = (size_t)m * HID + n;
                    const float2 rr = *reinterpret_cast<const float2*>(resid + off);
                    *reinterpret_cast<float2*>(outp + off) =
                        make_float2(v0 + rr.x, v1 + rr.y);
                } else {
                    const int part = n >> 10;
                    const int h = (n & 1023) >> 6;
                    const int d = n & 63;
                    const size_t off =
                        (((size_t)(b_ * NHEAD + h)) * SEQ + s_) * DH + d;
                    if (part == 0) {
                        v0 *= 0.125f; v1 *= 0.125f;   // fold 1/sqrt(DH)
                        __nv_bfloat16 h0 = __float2bfloat16(v0);
                        __nv_bfloat16 h1 = __float2bfloat16(v1);
                        *reinterpret_cast<__nv_bfloat162*>(g_qh + off) =
                            __halves2bfloat162(h0, h1);
                        *reinterpret_cast<__nv_bfloat162*>(g_ql + off) =
                            __halves2bfloat162(
                                __float2bfloat16(v0 - __bfloat162float(h0)),
                                __float2bfloat16(v1 - __bfloat162float(h1)));
                    } else if (part == 1) {
                        __nv_bfloat16 h0 = __float2bfloat16(v0);
                        __nv_bfloat16 h1 = __float2bfloat16(v1);
                        *reinterpret_cast<__nv_bfloat162*>(g_kh + off) =
                            __halves2bfloat162(h0, h1);
                        *reinterpret_cast<__nv_bfloat162*>(g_kl + off) =
                            __halves2bfloat162(
                                __float2bfloat16(v0 - __bfloat162float(h0)),
                                __float2bfloat16(v1 - __bfloat162float(h1)));
                    } else {
                        *reinterpret_cast<__nv_bfloat162*>(g_vh + off) =
                            __halves2bfloat162(__float2bfloat16(v0),
                                               __float2bfloat16(v1));
                    }
                }
            }
        }
    }
}

// ---------------------------------------------------------------------------
// 4) Tensor-core flash attention, 3-stage KV pipeline, one barrier per tile.
//    Grid (16 q-tiles, 64 bh), 256 threads = 8 warps, warp owns 16 q-rows.
//    Output -> g_ah only (OUT GEMM is single-term).
// ---------------------------------------------------------------------------
#define AQ_L   16384
#define ABUF   32768
#define ABUFS  25856
#define AK_L   8192
#define AV     16384
#define AMSK   25600
#define AT_SMEM (ABUF + 3 * ABUFS)   // 110336

__global__ __launch_bounds__(256) void attn_kernel(const float* __restrict__ mask)
{
    extern __shared__ char smem[];
    const uint32_t sb = smem_u32(smem);
    const int tid  = threadIdx.x;
    const int lane = tid & 31;
    const int wid  = tid >> 5;
    const int bh   = blockIdx.y;
    const int b    = bh >> 4;
    const int h    = bh & 15;
    const int qt   = blockIdx.x;

    const __nv_bfloat16* Qh = g_qh + ((size_t)bh * SEQ + (size_t)qt * 128) * DH;
    const __nv_bfloat16* Ql = g_ql + ((size_t)bh * SEQ + (size_t)qt * 128) * DH;
    const __nv_bfloat16* Kh = g_kh + (size_t)bh * SEQ * DH;
    const __nv_bfloat16* Kl = g_kl + (size_t)bh * SEQ * DH;
    const __nv_bfloat16* Vv = g_vh + (size_t)bh * SEQ * DH;
    const float* mk = mask + (size_t)b * SEQ;

    // ---- load Q tile (128 rows x 64, hi+lo): 2048 16B chunks ----
    #pragma unroll
    for (int it = 0; it < 8; it++) {
        const int c   = it * 256 + tid;
        const int arr = c >> 10;
        const int cc  = c & 1023;
        const int r   = cc >> 3, j = cc & 7;
        const uint32_t soff = (uint32_t)((arr ? AQ_L : 0) + r * 128 +
                                         ((j ^ (r & 7)) << 4));
        cp16(sb + soff, (arr ? Ql : Qh) + (size_t)r * DH + j * 8);
    }

    auto load_kv = [&](int kt, int buf) {
        const uint32_t base = sb + ABUF + (uint32_t)buf * ABUFS;
        #pragma unroll
        for (int it = 0; it < 7; it++) {
            const int c = it * 256 + tid;
            if (c < 1536) {
                const int arr = c >> 9;     // 0 KH, 1 KL, 2 V
                const int cc  = c & 511;
                const int r   = cc >> 3, j = cc & 7;
                if (arr < 2) {
                    const uint32_t soff = (uint32_t)((arr ? AK_L : 0) + r * 128 +
                                                     ((j ^ (r & 7)) << 4));
                    cp16(base + soff,
                         (arr ? Kl : Kh) + ((size_t)kt * 64 + r) * DH + j * 8);
                } else {
                    cp16(base + AV + (uint32_t)(r * 144 + j * 16),
                         Vv + ((size_t)kt * 64 + r) * DH + j * 8);
                }
            } else if (c < 1552) {
                const int j = c - 1536;
                cp16(base + AMSK + (uint32_t)(j * 16), mk + kt * 64 + j * 4);
            }
        }
    };

    float O[8][4];
    #pragma unroll
    for (int i = 0; i < 8; i++)
        #pragma unroll
        for (int j = 0; j < 4; j++) O[i][j] = 0.f;
    float m_run[2] = {-1e30f, -1e30f};
    float l_run[2] = {0.f, 0.f};

    load_kv(0, 0);
    CP_COMMIT();
    load_kv(1, 1);
    CP_COMMIT();

    int cur = 0;
    for (int kt = 0; kt < SEQ / 64; kt++) {
        if (kt + 2 < SEQ / 64) { CP_WAIT1(); } else { CP_WAIT0(); }
        __syncthreads();
        if (kt + 2 < SEQ / 64) {
            int nb = cur + 2; if (nb >= 3) nb -= 3;
            load_kv(kt + 2, nb);
            CP_COMMIT();
        }

        const uint32_t kbase = sb + ABUF + (uint32_t)cur * ABUFS;

        // ---- S = Q' @ K^T  (3-term split) ----
        float C[8][4];
        #pragma unroll
        for (int i = 0; i < 8; i++)
            #pragma unroll
            for (int j = 0; j < 4; j++) C[i][j] = 0.f;

        #pragma unroll
        for (int kd = 0; kd < 4; kd++) {
            uint32_t ah[4], al[4];
            {
                const int r  = wid * 16 + (lane & 15);
                const int jc = kd * 2 + (lane >> 4);
                const uint32_t addr = sb + (uint32_t)(r * 128 +
                                        ((jc ^ (r & 7)) << 4));
                ldsm_x4(ah, addr);
                ldsm_x4(al, addr + AQ_L);
            }
            #pragma unroll
            for (int p = 0; p < 4; p++) {
                const int r  = p * 16 + (lane & 7) + ((lane >> 4) << 3);
                const int jc = kd * 2 + ((lane >> 3) & 1);
                const uint32_t addr = kbase + (uint32_t)(r * 128 +
                                        ((jc ^ (r & 7)) << 4));
                uint32_t th[4], tl[4];
                ldsm_x4(th, addr);
                ldsm_x4(tl, addr + AK_L);
                mma_bf16(C[2 * p],     ah, th);
                mma_bf16(C[2 * p],     ah, tl);
                mma_bf16(C[2 * p],     al, th);
                mma_bf16(C[2 * p + 1], ah, th + 2);
                mma_bf16(C[2 * p + 1], ah, tl + 2);
                mma_bf16(C[2 * p + 1], al, th + 2);
            }
        }

        // ---- online softmax (rows g = lane>>2 and g+8) ----
        const float* msk = reinterpret_cast<const float*>(
            smem + ABUF + (size_t)cur * ABUFS + AMSK);
        const int c0 = (lane & 3) * 2;

        float mloc0 = -1e30f, mloc1 = -1e30f;
        #pragma unroll
        for (int nt = 0; nt < 8; nt++) {
            const float mv0 = msk[nt * 8 + c0];
            const float mv1 = msk[nt * 8 + c0 + 1];
            C[nt][0] += mv0; C[nt][1] += mv1;
            C[nt][2] += mv0; C[nt][3] += mv1;
            mloc0 = fmaxf(mloc0, fmaxf(C[nt][0], C[nt][1]));
            mloc1 = fmaxf(mloc1, fmaxf(C[nt][2], C[nt][3]));
        }
        mloc0 = fmaxf(mloc0, __shfl_xor_sync(0xffffffffu, mloc0, 1));
        mloc0 = fmaxf(mloc0, __shfl_xor_sync(0xffffffffu, mloc0, 2));
        mloc1 = fmaxf(mloc1, __shfl_xor_sync(0xffffffffu, mloc1, 1));
        mloc1 = fmaxf(mloc1, __shfl_xor_sync(0xffffffffu, mloc1, 2));

        const float mnew0 = fmaxf(m_run[0], mloc0);
        const float mnew1 = fmaxf(m_run[1], mloc1);
        const float corr0 = __expf(m_run[0] - mnew0);
        const float corr1 = __expf(m_run[1] - mnew1);

        float ls0 = 0.f, ls1 = 0.f;
        #pragma unroll
        for (int nt = 0; nt < 8; nt++) {
            C[nt][0] = __expf(C[nt][0] - mnew0);
            C[nt][1] = __expf(C[nt][1] - mnew0);
            C[nt][2] = __expf(C[nt][2] - mnew1);
            C[nt][3] = __expf(C[nt][3] - mnew1);
            ls0 += C[nt][0] + C[nt][1];
            ls1 += C[nt][2] + C[nt][3];
        }
        ls0 += __shfl_xor_sync(0xffffffffu, ls0, 1);
        ls0 += __shfl_xor_sync(0xffffffffu, ls0, 2);
        ls1 += __shfl_xor_sync(0xffffffffu, ls1, 1);
        ls1 += __shfl_xor_sync(0xffffffffu, ls1, 2);

        l_run[0] = l_run[0] * corr0 + ls0;
        l_run[1] = l_run[1] * corr1 + ls1;
        m_run[0] = mnew0;
        m_run[1] = mnew1;

        #pragma unroll
        for (int nt = 0; nt < 8; nt++) {
            O[nt][0] *= corr0; O[nt][1] *= corr0;
            O[nt][2] *= corr1; O[nt][3] *= corr1;
        }

        // ---- pack P (C-frag -> A-frag identity) ----
        uint32_t pa[4][4];
        #pragma unroll
        for (int kc = 0; kc < 4; kc++) {
            pa[kc][0] = pack_bf16(C[2 * kc][0],     C[2 * kc][1]);
            pa[kc][1] = pack_bf16(C[2 * kc][2],     C[2 * kc][3]);
            pa[kc][2] = pack_bf16(C[2 * kc + 1][0], C[2 * kc + 1][1]);
            pa[kc][3] = pack_bf16(C[2 * kc + 1][2], C[2 * kc + 1][3]);
        }

        // ---- O += P @ V ----
        #pragma unroll
        for (int kc = 0; kc < 4; kc++) {
            #pragma unroll
            for (int np = 0; np < 4; np++) {
                const int r = kc * 16 + (lane & 7) + (((lane >> 3) & 1) << 3);
                const int jc = 2 * np + (lane >> 4);
                const uint32_t addr = kbase + AV + (uint32_t)(r * 144 + jc * 16);
                uint32_t t4[4];
                ldsm_x4_t(t4, addr);
                mma_bf16(O[2 * np],     pa[kc], t4);
                mma_bf16(O[2 * np + 1], pa[kc], t4 + 2);
            }
        }

        if (++cur == 3) cur = 0;
    }

    // ---- epilogue: normalize, write bf16 hi into g_ah [b][s][h*64+d] ----
    const float inv0 = 1.0f / l_run[0];
    const float inv1 = 1.0f / l_run[1];
    const int g  = lane >> 2;
    const int s0 = qt * 128 + wid * 16 + g;
    const int c0 = (lane & 3) * 2;

    #pragma unroll
    for (int nt = 0; nt < 8; nt++) {
        const int d = h * DH + nt * 8 + c0;
        {
            const size_t off = ((size_t)b * SEQ + s0) * HID + d;
            *reinterpret_cast<__nv_bfloat162*>(g_ah + off) =
                __halves2bfloat162(__float2bfloat16(O[nt][0] * inv0),
                                   __float2bfloat16(O[nt][1] * inv0));
        }
        {
            const size_t off = ((size_t)b * SEQ + s0 + 8) * HID + d;
            *reinterpret_cast<__nv_bfloat162*>(g_ah + off) =
                __halves2bfloat162(__float2bfloat16(O[nt][2] * inv1),
                                   __float2bfloat16(O[nt][3] * inv1));
        }
    }
}

// ---------------------------------------------------------------------------
// kernel_launch
// ---------------------------------------------------------------------------
extern "C" void kernel_launch(void* const* d_in, const int* in_sizes, int n_in,
                              void* d_out, int out_size)
{
    (void)in_sizes; (void)n_in; (void)out_size;
    const float* hidden = (const float*)d_in[0];
    const float* mask   = (const float*)d_in[1];
    const float* gamma  = (const float*)d_in[2];
    const float* beta   = (const float*)d_in[3];
    const float* Wqkv   = (const float*)d_in[4];
    const float* bqkv   = (const float*)d_in[5];
    const float* Wout   = (const float*)d_in[6];
    const float* bout   = (const float*)d_in[7];
    float* out = (float*)d_out;

    cudaFuncSetAttribute(mm_kernel<0>,
                         cudaFuncAttributeMaxDynamicSharedMemorySize, MM0_SMEM);
    cudaFuncSetAttribute(mm_kernel<1>,
                         cudaFuncAttributeMaxDynamicSharedMemorySize, MM1_SMEM);
    cudaFuncSetAttribute(attn_kernel,
                         cudaFuncAttributeMaxDynamicSharedMemorySize, AT_SMEM);

    ln_kernel<<<NTOK, 256>>>(hidden, gamma, beta);
    conv_w<<<dim3(3 * HID / 32, HID / 32), dim3(32, 8)>>>(Wqkv, 0, 3 * HID);
    conv_w<<<dim3(HID / 32, HID / 32), dim3(32, 8)>>>(Wout, 1, HID);
    mm_kernel<0><<<dim3(3 * HID / 128, NTOK / 128), 256, MM0_SMEM>>>(bqkv, nullptr, nullptr);
    attn_kernel<<<dim3(SEQ / 128, BATCH * NHEAD), 256, AT_SMEM>>>(mask);
    mm_kernel<1><<<dim3(HID / 128, NTOK / 128), 256, MM1_SMEM>>>(bout, hidden, out);
}